// round 8
// baseline (speedup 1.0000x reference)
#include <cuda_runtime.h>
#include <cuda_bf16.h>
#include <math.h>
#include <stdint.h>

#define Bm 4
#define Tt 2048
#define Cc 1024
#define Hh 16
#define Dd 64
#define Mrows (Bm*Tt)   // 8192

// ------------------------- device-global scratch ---------------------------
__device__ __nv_bfloat16 g_qh[Bm*Hh*Tt*Dd];  // [B,H,T,D] bf16 hi (pre-scaled 1/8)
__device__ __nv_bfloat16 g_ql[Bm*Hh*Tt*Dd];
__device__ __nv_bfloat16 g_kh[Bm*Hh*Tt*Dd];
__device__ __nv_bfloat16 g_kl[Bm*Hh*Tt*Dd];
__device__ __nv_bfloat16 g_vh[Bm*Hh*Tt*Dd];
__device__ __nv_bfloat16 g_vl[Bm*Hh*Tt*Dd];

__device__ __nv_bfloat16 g_xh[Mrows*Cc];
__device__ __nv_bfloat16 g_xl[Mrows*Cc];
__device__ __nv_bfloat16 g_yh[Mrows*Cc];
__device__ __nv_bfloat16 g_yl[Mrows*Cc];
__device__ __nv_bfloat16 g_wh[4*Cc*Cc];
__device__ __nv_bfloat16 g_wl[4*Cc*Cc];

// ---------------------------------------------------------------------------
// single fused split kernel: fp32 -> bf16 hi + lo for x and the 4 weights
// grid: 8192 blocks for x, then 4 x 1024 for Wq,Wk,Wv,Wp
// ---------------------------------------------------------------------------
__global__ void split_all(const float* __restrict__ x,
                          const float* __restrict__ Wq, const float* __restrict__ Wk,
                          const float* __restrict__ Wv, const float* __restrict__ Wp)
{
    const int bi = blockIdx.x;
    const int tid = threadIdx.x;
    const float* src;
    __nv_bfloat16 *hi, *lo;
    int i;
    if (bi < 8192) {
        src = x; hi = g_xh; lo = g_xl;
        i = (bi * 256 + tid) * 4;
    } else {
        int r = bi - 8192;
        int which = r >> 10;
        src = (which == 0) ? Wq : (which == 1) ? Wk : (which == 2) ? Wv : Wp;
        hi = g_wh + (size_t)which * Cc * Cc;
        lo = g_wl + (size_t)which * Cc * Cc;
        i = (((r & 1023) * 256) + tid) * 4;
    }

    float4 v = *(const float4*)(src + i);
    __nv_bfloat16 h0 = __float2bfloat16_rn(v.x);
    __nv_bfloat16 h1 = __float2bfloat16_rn(v.y);
    __nv_bfloat16 h2 = __float2bfloat16_rn(v.z);
    __nv_bfloat16 h3 = __float2bfloat16_rn(v.w);
    hi[i+0] = h0; hi[i+1] = h1; hi[i+2] = h2; hi[i+3] = h3;
    lo[i+0] = __float2bfloat16_rn(v.x - __bfloat162float(h0));
    lo[i+1] = __float2bfloat16_rn(v.y - __bfloat162float(h1));
    lo[i+2] = __float2bfloat16_rn(v.z - __bfloat162float(h2));
    lo[i+3] = __float2bfloat16_rn(v.w - __bfloat162float(h3));
}

// ---------------------------------------------------------------------------
// helpers
// ---------------------------------------------------------------------------
__device__ __forceinline__ uint32_t sptr(const void* p)
{ uint32_t a; asm("{ .reg .u64 t; cvta.to.shared.u64 t, %1; cvt.u32.u64 %0, t; }" : "=r"(a) : "l"(p)); return a; }

__device__ __forceinline__ uint32_t pk(float a, float b)
{
    __nv_bfloat162 t = __floats2bfloat162_rn(a, b);
    return *(uint32_t*)&t;
}

__device__ __forceinline__ void mma16816(float* c, const uint32_t* a, const uint32_t* b)
{
    asm volatile(
        "mma.sync.aligned.m16n8k16.row.col.f32.bf16.bf16.f32 "
        "{%0,%1,%2,%3}, {%4,%5,%6,%7}, {%8,%9}, {%0,%1,%2,%3};\n"
        : "+f"(c[0]), "+f"(c[1]), "+f"(c[2]), "+f"(c[3])
        : "r"(a[0]), "r"(a[1]), "r"(a[2]), "r"(a[3]), "r"(b[0]), "r"(b[1]));
}
__device__ __forceinline__ void ldm4(uint32_t* r, uint32_t a)
{
    asm volatile("ldmatrix.sync.aligned.m8n8.x4.shared.b16 {%0,%1,%2,%3}, [%4];"
        : "=r"(r[0]), "=r"(r[1]), "=r"(r[2]), "=r"(r[3]) : "r"(a));
}
__device__ __forceinline__ void ldm4t(uint32_t* r, uint32_t a)
{
    asm volatile("ldmatrix.sync.aligned.m8n8.x4.trans.shared.b16 {%0,%1,%2,%3}, [%4];"
        : "=r"(r[0]), "=r"(r[1]), "=r"(r[2]), "=r"(r[3]) : "r"(a));
}

// bulk-async: one 128B row per instruction, completion via mbarrier tx-bytes
__device__ __forceinline__ void bulk128(uint32_t dst, const void* src, uint32_t mb)
{
    asm volatile(
        "cp.async.bulk.shared::cluster.global.mbarrier::complete_tx::bytes [%0], [%1], 128, [%2];"
        :: "r"(dst), "l"(src), "r"(mb) : "memory");
}
__device__ __forceinline__ void mb_init(uint32_t mb, uint32_t cnt)
{ asm volatile("mbarrier.init.shared.b64 [%0], %1;" :: "r"(mb), "r"(cnt) : "memory"); }
__device__ __forceinline__ void mb_expect(uint32_t mb, uint32_t bytes)
{ asm volatile("mbarrier.arrive.expect_tx.shared.b64 _, [%0], %1;" :: "r"(mb), "r"(bytes) : "memory"); }
__device__ __forceinline__ void mb_wait(uint32_t mb, uint32_t ph)
{
    uint32_t done = 0;
    while (!done) {
        asm volatile(
            "{\n\t.reg .pred p;\n\t"
            "mbarrier.try_wait.parity.shared.b64 p, [%1], %2;\n\t"
            "selp.b32 %0, 1, 0, p;\n\t}"
            : "=r"(done) : "r"(mb), "r"(ph) : "memory");
    }
}

// ---------------------------------------------------------------------------
// Bulk-async split-bf16 GEMM. C = A @ W^T + bias. CTA tile 128(M) x 256(N),
// 8 warps (2M x 4N), warp tile 64x64. K-chunk 64 (128B rows, pitch 144B),
// double-buffered via cp.async.bulk + mbarrier.
// fused=1: blockIdx.z selects Wq/Wk/Wv -> split-epilogue to QKV [B,H,T,D].
// fused=0: fp32 linear to outp.
// smem: 2 x 110592B buffers + 16B mbarriers = 221200 B dynamic.
// ---------------------------------------------------------------------------
#define GB_BUF   110592
#define GB_AH    0
#define GB_AL    18432
#define GB_BH    36864
#define GB_BL    73728
#define GB_MBAR  (2*GB_BUF)
#define GB_SMEM  (2*GB_BUF + 16)
#define GB_BYTES 98304       // 768 rows x 128B per chunk

__global__ __launch_bounds__(256, 1) void gemm_bulk(
    const __nv_bfloat16* __restrict__ Ah, const __nv_bfloat16* __restrict__ Al,
    const __nv_bfloat16* __restrict__ Wh, const __nv_bfloat16* __restrict__ Wl,
    const float* __restrict__ b0, const float* __restrict__ b1,
    const float* __restrict__ b2,
    float* __restrict__ outp, int fused)
{
    extern __shared__ char smem[];
    const uint32_t sb = sptr(smem);

    const int which = blockIdx.z;
    const __nv_bfloat16* __restrict__ Bh = Wh + (size_t)which * Cc * Cc;
    const __nv_bfloat16* __restrict__ Bl = Wl + (size_t)which * Cc * Cc;
    const float* __restrict__ bias = (which == 0) ? b0 : (which == 1) ? b1 : b2;
    const int mode = fused ? which : 3;

    const int tid  = threadIdx.x;
    const int warp = tid >> 5;
    const int lane = tid & 31;
    const int warpM = warp & 1;
    const int warpN = warp >> 1;
    const int gid = lane >> 2;
    const int tig = lane & 3;

    const int rowBase = blockIdx.y * 128;
    const int colBase = blockIdx.x * 256;

    if (tid == 0) { mb_init(sb + GB_MBAR, 1); mb_init(sb + GB_MBAR + 8, 1); }
    __syncthreads();

    float acc[4][8][4];
    #pragma unroll
    for (int i = 0; i < 4; i++)
        #pragma unroll
        for (int j = 0; j < 8; j++)
            #pragma unroll
            for (int k = 0; k < 4; k++) acc[i][j][k] = 0.0f;

    // each thread copies 3 of the 768 rows per chunk
    auto issue = [&](int s, int buf) {
        const int k0 = s * 64;
        const uint32_t bb = sb + buf * GB_BUF;
        const uint32_t mb = sb + GB_MBAR + buf * 8;
        #pragma unroll
        for (int it = 0; it < 3; it++) {
            int rho = tid + it * 256;
            const __nv_bfloat16* src;
            uint32_t dst;
            if (rho < 128) {
                src = Ah + (size_t)(rowBase + rho) * Cc + k0;
                dst = bb + GB_AH + rho * 144;
            } else if (rho < 256) {
                int r = rho - 128;
                src = Al + (size_t)(rowBase + r) * Cc + k0;
                dst = bb + GB_AL + r * 144;
            } else if (rho < 512) {
                int r = rho - 256;
                src = Bh + (size_t)(colBase + r) * Cc + k0;
                dst = bb + GB_BH + r * 144;
            } else {
                int r = rho - 512;
                src = Bl + (size_t)(colBase + r) * Cc + k0;
                dst = bb + GB_BL + r * 144;
            }
            bulk128(dst, src, mb);
        }
    };

    // prologue: arm both barriers, then issue chunks 0 and 1
    if (tid == 0) { mb_expect(sb + GB_MBAR, GB_BYTES); mb_expect(sb + GB_MBAR + 8, GB_BYTES); }
    __syncthreads();
    issue(0, 0);
    issue(1, 1);

    for (int s = 0; s < 16; s++) {
        const int buf = s & 1;
        mb_wait(sb + GB_MBAR + buf * 8, (s >> 1) & 1);
        if (tid == 0 && s + 2 < 16) mb_expect(sb + GB_MBAR + buf * 8, GB_BYTES);

        const __nv_bfloat16* base = (const __nv_bfloat16*)(smem) + buf * (GB_BUF / 2);
        const __nv_bfloat16* sAh = base;
        const __nv_bfloat16* sAl = base + GB_AL / 2;
        const __nv_bfloat16* sBh = base + GB_BH / 2;
        const __nv_bfloat16* sBl = base + GB_BL / 2;

        #pragma unroll
        for (int sub = 0; sub < 4; sub++) {
            const int colE = sub * 16 + (lane >> 4) * 8;   // elements

            uint32_t bhf[8][2], blf[8][2];
            #pragma unroll
            for (int grp = 0; grp < 4; grp++) {
                int row = warpN * 64 + grp * 16 + (lane & 15);
                uint32_t t[4];
                ldm4(t, sptr(sBh + row * 72 + colE));
                bhf[2*grp][0]   = t[0]; bhf[2*grp][1]   = t[2];
                bhf[2*grp+1][0] = t[1]; bhf[2*grp+1][1] = t[3];
                ldm4(t, sptr(sBl + row * 72 + colE));
                blf[2*grp][0]   = t[0]; blf[2*grp][1]   = t[2];
                blf[2*grp+1][0] = t[1]; blf[2*grp+1][1] = t[3];
            }

            #pragma unroll
            for (int mi = 0; mi < 4; mi++) {
                int row = warpM * 64 + mi * 16 + (lane & 15);
                uint32_t ah[4], al[4];
                ldm4(ah, sptr(sAh + row * 72 + colE));
                ldm4(al, sptr(sAl + row * 72 + colE));
                #pragma unroll
                for (int ni = 0; ni < 8; ni++) {
                    mma16816(acc[mi][ni], ah, bhf[ni]);
                    mma16816(acc[mi][ni], ah, blf[ni]);
                    mma16816(acc[mi][ni], al, bhf[ni]);
                }
            }
        }
        __syncthreads();
        if (s + 2 < 16) issue(s + 2, buf);
    }

    // ---- epilogue ----
    if (mode == 3) {
        #pragma unroll
        for (int mi = 0; mi < 4; mi++) {
            #pragma unroll
            for (int ni = 0; ni < 8; ni++) {
                int m0 = rowBase + warpM * 64 + mi * 16 + gid;
                int n0 = colBase + warpN * 64 + ni * 8 + tig * 2;
                #pragma unroll
                for (int e = 0; e < 4; e++) {
                    int m = m0 + ((e >> 1) ? 8 : 0);
                    int n = n0 + (e & 1);
                    outp[(size_t)m * Cc + n] = acc[mi][ni][e] + bias[n];
                }
            }
        }
    } else {
        __nv_bfloat16* dh = (mode == 0) ? g_qh : (mode == 1) ? g_kh : g_vh;
        __nv_bfloat16* dl = (mode == 0) ? g_ql : (mode == 1) ? g_kl : g_vl;
        const float sc = (mode == 0) ? 0.125f : 1.0f;

        #pragma unroll
        for (int mi = 0; mi < 4; mi++) {
            #pragma unroll
            for (int ni = 0; ni < 8; ni++) {
                int m0 = rowBase + warpM * 64 + mi * 16 + gid;
                int n0 = colBase + warpN * 64 + ni * 8 + tig * 2;
                #pragma unroll
                for (int half = 0; half < 2; half++) {
                    int m = m0 + half * 8;
                    float v0 = (acc[mi][ni][half*2+0] + bias[n0])   * sc;
                    float v1 = (acc[mi][ni][half*2+1] + bias[n0+1]) * sc;
                    __nv_bfloat16 h0 = __float2bfloat16_rn(v0);
                    __nv_bfloat16 h1 = __float2bfloat16_rn(v1);
                    int b = m >> 11, t = m & 2047;
                    int h = n0 >> 6, d = n0 & 63;
                    size_t off = (((size_t)(b * Hh + h)) * Tt + t) * Dd + d;
                    __nv_bfloat162 hp; hp.x = h0; hp.y = h1;
                    *(uint32_t*)(dh + off) = *(uint32_t*)&hp;
                    *(uint32_t*)(dl + off) = pk(v0 - __bfloat162float(h0),
                                                v1 - __bfloat162float(h1));
                }
            }
        }
    }
}

// ---------------------------------------------------------------------------
// Flash attention, split-bf16, causal, bulk-async double-buffered K/V.
// Grid (16, 64), 256 threads (8 warps x 16 q-rows). K/V tiles of 64 keys.
// smem layout (dynamic): buf0 36864 | buf1 36864 | Q 36864 | mbar 16 = 110608
//   each KV buffer: kh 9216 | kl 9216 | vh 9216 | vl 9216   (pitch 144B rows)
// ---------------------------------------------------------------------------
#define AT_BUF   36864
#define AT_Q     (2*AT_BUF)
#define AT_MBAR  (AT_Q + 36864)
#define AT_SMEM  (AT_MBAR + 16)
#define AT_BYTES 32768       // 256 rows x 128B per tile

__global__ __launch_bounds__(256, 1) void attn_mma()
{
    extern __shared__ char sm[];
    const uint32_t sbase = sptr(sm);

    const int bh = blockIdx.y;
    const int qblk = (int)gridDim.x - 1 - (int)blockIdx.x;  // heavy blocks first
    const int tid = threadIdx.x;
    const int warp = tid >> 5;
    const int lane = tid & 31;
    const int g = lane >> 2;
    const int tig = lane & 3;

    const size_t base = (size_t)bh * Tt * Dd;

    if (tid == 0) { mb_init(sbase + AT_MBAR, 1); mb_init(sbase + AT_MBAR + 8, 1); }

    // ---- stage Q tile (pitch 72 elems), build A-fragments ----
    {
        __nv_bfloat16* sQh = (__nv_bfloat16*)(sm + AT_Q);
        __nv_bfloat16* sQl = sQh + 128*72;
        #pragma unroll
        for (int it = 0; it < 4; it++) {
            int idx = tid + it * 256;
            int r = idx >> 3, c8 = (idx & 7) * 8;
            size_t goff = base + (size_t)(qblk*128 + r) * Dd + c8;
            *(uint4*)(sQh + r*72 + c8) = *(const uint4*)(g_qh + goff);
            *(uint4*)(sQl + r*72 + c8) = *(const uint4*)(g_ql + goff);
        }
    }
    __syncthreads();

    uint32_t qfh[4][4], qfl[4][4];
    {
        const __nv_bfloat16* sQh = (const __nv_bfloat16*)(sm + AT_Q);
        const __nv_bfloat16* sQl = sQh + 128*72;
        int row = warp*16 + (lane & 15);
        #pragma unroll
        for (int kt = 0; kt < 4; kt++) {
            int col = kt*16 + (lane >> 4) * 8;
            ldm4(qfh[kt], sptr(sQh + row*72 + col));
            ldm4(qfl[kt], sptr(sQl + row*72 + col));
        }
    }

    float o[8][4];
    #pragma unroll
    for (int i = 0; i < 8; i++)
        #pragma unroll
        for (int j = 0; j < 4; j++) o[i][j] = 0.0f;

    float mA = -INFINITY, mB = -INFINITY, lA = 0.0f, lB = 0.0f;
    const int wr0 = qblk*128 + warp*16;
    const int ntiles = 2*qblk + 2;

    // one row per thread: array = tid>>6 (kh,kl,vh,vl), r = tid&63
    auto issue = [&](int ti, int buf) {
        const int kb = ti * 64;
        const uint32_t bb = sbase + buf * AT_BUF;
        const uint32_t mb = sbase + AT_MBAR + buf * 8;
        const int arr = tid >> 6, r = tid & 63;
        const __nv_bfloat16* src =
            (arr == 0) ? g_kh : (arr == 1) ? g_kl : (arr == 2) ? g_vh : g_vl;
        bulk128(bb + arr * 9216 + r * 144, src + base + (size_t)(kb + r) * Dd, mb);
    };

    __syncthreads();   // mbar init + Q frags done everywhere
    if (tid == 0) { mb_expect(sbase + AT_MBAR, AT_BYTES); mb_expect(sbase + AT_MBAR + 8, AT_BYTES); }
    __syncthreads();
    issue(0, 0);
    issue(1, 1);

    for (int ti = 0; ti < ntiles; ti++) {
        const int kb = ti * 64;
        const int buf = ti & 1;
        mb_wait(sbase + AT_MBAR + buf * 8, (ti >> 1) & 1);
        if (tid == 0 && ti + 2 < ntiles) mb_expect(sbase + AT_MBAR + buf * 8, AT_BYTES);

        const char* bb = sm + buf * AT_BUF;
        const __nv_bfloat16* sKh = (const __nv_bfloat16*)(bb + 0*9216);
        const __nv_bfloat16* sKl = (const __nv_bfloat16*)(bb + 1*9216);
        const __nv_bfloat16* sVh = (const __nv_bfloat16*)(bb + 2*9216);
        const __nv_bfloat16* sVl = (const __nv_bfloat16*)(bb + 3*9216);

        // ---- S = Q K^T (3-term split) ----
        float s[8][4];
        #pragma unroll
        for (int i = 0; i < 8; i++)
            #pragma unroll
            for (int j = 0; j < 4; j++) s[i][j] = 0.0f;

        #pragma unroll
        for (int kt = 0; kt < 4; kt++) {
            uint32_t kh4[4][4], kl4[4][4];
            #pragma unroll
            for (int i = 0; i < 4; i++) {
                int row = i*16 + (lane & 15);
                int col = kt*16 + (lane >> 4) * 8;
                ldm4(kh4[i], sptr(sKh + row*72 + col));
                ldm4(kl4[i], sptr(sKl + row*72 + col));
            }
            #pragma unroll
            for (int i = 0; i < 4; i++) {
                uint32_t b0h[2] = {kh4[i][0], kh4[i][2]};
                uint32_t b1h[2] = {kh4[i][1], kh4[i][3]};
                uint32_t b0l[2] = {kl4[i][0], kl4[i][2]};
                uint32_t b1l[2] = {kl4[i][1], kl4[i][3]};
                mma16816(s[2*i],   qfh[kt], b0h);
                mma16816(s[2*i],   qfh[kt], b0l);
                mma16816(s[2*i],   qfl[kt], b0h);
                mma16816(s[2*i+1], qfh[kt], b1h);
                mma16816(s[2*i+1], qfh[kt], b1l);
                mma16816(s[2*i+1], qfl[kt], b1h);
            }
        }

        // ---- causal mask ----
        if (kb + 64 > wr0) {
            int rA = wr0 + g, rB = rA + 8;
            #pragma unroll
            for (int nt = 0; nt < 8; nt++) {
                int c0 = kb + nt*8 + tig*2;
                if (c0     > rA) s[nt][0] = -INFINITY;
                if (c0 + 1 > rA) s[nt][1] = -INFINITY;
                if (c0     > rB) s[nt][2] = -INFINITY;
                if (c0 + 1 > rB) s[nt][3] = -INFINITY;
            }
        }

        // ---- online softmax ----
        float ma = -INFINITY, mb2 = -INFINITY;
        #pragma unroll
        for (int nt = 0; nt < 8; nt++) {
            ma  = fmaxf(ma,  fmaxf(s[nt][0], s[nt][1]));
            mb2 = fmaxf(mb2, fmaxf(s[nt][2], s[nt][3]));
        }
        ma  = fmaxf(ma,  __shfl_xor_sync(0xffffffff, ma, 1));
        ma  = fmaxf(ma,  __shfl_xor_sync(0xffffffff, ma, 2));
        mb2 = fmaxf(mb2, __shfl_xor_sync(0xffffffff, mb2, 1));
        mb2 = fmaxf(mb2, __shfl_xor_sync(0xffffffff, mb2, 2));

        float nmA = fmaxf(mA, ma), nmB = fmaxf(mB, mb2);
        float cA = __expf(mA - nmA), cB = __expf(mB - nmB);
        mA = nmA; mB = nmB;
        lA *= cA; lB *= cB;
        #pragma unroll
        for (int nt = 0; nt < 8; nt++) {
            o[nt][0] *= cA; o[nt][1] *= cA;
            o[nt][2] *= cB; o[nt][3] *= cB;
        }

        uint32_t pah[4][4], pal[4][4];
        float suA = 0.0f, suB = 0.0f;
        #pragma unroll
        for (int nt = 0; nt < 8; nt++) {
            float p0 = __expf(s[nt][0] - nmA);
            float p1 = __expf(s[nt][1] - nmA);
            float p2 = __expf(s[nt][2] - nmB);
            float p3 = __expf(s[nt][3] - nmB);
            suA += p0 + p1; suB += p2 + p3;
            __nv_bfloat16 h0 = __float2bfloat16_rn(p0);
            __nv_bfloat16 h1 = __float2bfloat16_rn(p1);
            __nv_bfloat16 h2 = __float2bfloat16_rn(p2);
            __nv_bfloat16 h3 = __float2bfloat16_rn(p3);
            int kt = nt >> 1, hi2 = (nt & 1) * 2;
            __nv_bfloat162 t01; t01.x = h0; t01.y = h1;
            __nv_bfloat162 t23; t23.x = h2; t23.y = h3;
            pah[kt][hi2 + 0] = *(uint32_t*)&t01;
            pah[kt][hi2 + 1] = *(uint32_t*)&t23;
            pal[kt][hi2 + 0] = pk(p0 - __bfloat162float(h0), p1 - __bfloat162float(h1));
            pal[kt][hi2 + 1] = pk(p2 - __bfloat162float(h2), p3 - __bfloat162float(h3));
        }
        suA += __shfl_xor_sync(0xffffffff, suA, 1);
        suA += __shfl_xor_sync(0xffffffff, suA, 2);
        suB += __shfl_xor_sync(0xffffffff, suB, 1);
        suB += __shfl_xor_sync(0xffffffff, suB, 2);
        lA += suA; lB += suB;

        // ---- O += P V (3-term split) ----
        #pragma unroll
        for (int kt = 0; kt < 4; kt++) {
            uint32_t vh4[4][4], vl4[4][4];
            #pragma unroll
            for (int j = 0; j < 4; j++) {
                int row = kt*16 + (lane & 15);
                int col = j*16 + (lane >> 4) * 8;
                ldm4t(vh4[j], sptr(sVh + row*72 + col));
                ldm4t(vl4[j], sptr(sVl + row*72 + col));
            }
            #pragma unroll
            for (int j = 0; j < 4; j++) {
                uint32_t b0h[2] = {vh4[j][0], vh4[j][1]};
                uint32_t b1h[2] = {vh4[j][2], vh4[j][3]};
                uint32_t b0l[2] = {vl4[j][0], vl4[j][1]};
                uint32_t b1l[2] = {vl4[j][2], vl4[j][3]};
                mma16816(o[2*j],   pah[kt], b0h);
                mma16816(o[2*j],   pah[kt], b0l);
                mma16816(o[2*j],   pal[kt], b0h);
                mma16816(o[2*j+1], pah[kt], b1h);
                mma16816(o[2*j+1], pah[kt], b1l);
                mma16816(o[2*j+1], pal[kt], b1h);
            }
        }
        __syncthreads();
        if (ti + 2 < ntiles) issue(ti + 2, buf);
    }

    // ---- epilogue: normalize, split to bf16 hi/lo, write [B,T,C] ----
    const float iA = 1.0f / lA, iB = 1.0f / lB;
    const int b = bh >> 4, h = bh & 15;
    const int rA = qblk*128 + warp*16 + g;
    const size_t offA = ((size_t)(b * Tt + rA)) * Cc + h * 64;
    const size_t offB = offA + (size_t)8 * Cc;

    #pragma unroll
    for (int nt = 0; nt < 8; nt++) {
        int c = nt*8 + tig*2;
        float y0 = o[nt][0] * iA, y1 = o[nt][1] * iA;
        float y2 = o[nt][2] * iB, y3 = o[nt][3] * iB;
        __nv_bfloat16 h0 = __float2bfloat16_rn(y0);
        __nv_bfloat16 h1 = __float2bfloat16_rn(y1);
        __nv_bfloat16 h2 = __float2bfloat16_rn(y2);
        __nv_bfloat16 h3 = __float2bfloat16_rn(y3);
        __nv_bfloat162 tA; tA.x = h0; tA.y = h1;
        __nv_bfloat162 tB; tB.x = h2; tB.y = h3;
        *(uint32_t*)(g_yh + offA + c) = *(uint32_t*)&tA;
        *(uint32_t*)(g_yh + offB + c) = *(uint32_t*)&tB;
        *(uint32_t*)(g_yl + offA + c) = pk(y0 - __bfloat162float(h0), y1 - __bfloat162float(h1));
        *(uint32_t*)(g_yl + offB + c) = pk(y2 - __bfloat162float(h2), y3 - __bfloat162float(h3));
    }
}

// ---------------------------------------------------------------------------
extern "C" void kernel_launch(void* const* d_in, const int* in_sizes, int n_in,
                              void* d_out, int out_size)
{
    const float* x  = (const float*)d_in[0];
    const float* Wq = (const float*)d_in[1];
    const float* bq = (const float*)d_in[2];
    const float* Wk = (const float*)d_in[3];
    const float* bk = (const float*)d_in[4];
    const float* Wv = (const float*)d_in[5];
    const float* bv = (const float*)d_in[6];
    const float* Wp = (const float*)d_in[7];
    const float* bp = (const float*)d_in[8];
    float* out = (float*)d_out;

    __nv_bfloat16 *xh, *xl, *yh, *yl, *wh, *wl;
    cudaGetSymbolAddress((void**)&xh, g_xh);
    cudaGetSymbolAddress((void**)&xl, g_xl);
    cudaGetSymbolAddress((void**)&yh, g_yh);
    cudaGetSymbolAddress((void**)&yl, g_yl);
    cudaGetSymbolAddress((void**)&wh, g_wh);
    cudaGetSymbolAddress((void**)&wl, g_wl);

    cudaFuncSetAttribute(gemm_bulk, cudaFuncAttributeMaxDynamicSharedMemorySize, GB_SMEM);
    cudaFuncSetAttribute(attn_mma, cudaFuncAttributeMaxDynamicSharedMemorySize, AT_SMEM);

    // all splits in one launch
    split_all<<<8192 + 4096, 256>>>(x, Wq, Wk, Wv, Wp);

    // fused QKV: one launch, z = 3
    const int nw = Cc * Cc;
    dim3 gQKV(Cc / 256, Mrows / 128, 3);
    gemm_bulk<<<gQKV, 256, GB_SMEM>>>(xh, xl, wh, wl, bq, bk, bv, nullptr, 1);

    dim3 gA(Tt / 128, Bm * Hh);
    attn_mma<<<gA, 256, AT_SMEM>>>();

    // out projection
    dim3 gO(Cc / 256, Mrows / 128, 1);
    gemm_bulk<<<gO, 256, GB_SMEM>>>(yh, yl, wh + 3*nw, wl + 3*nw, bp, bp, bp, out, 0);
}

// round 9
// speedup vs baseline: 1.2182x; 1.2182x over previous
#include <cuda_runtime.h>
#include <cuda_bf16.h>
#include <math.h>
#include <stdint.h>

#define Bm 4
#define Tt 2048
#define Cc 1024
#define Hh 16
#define Dd 64
#define Mrows (Bm*Tt)   // 8192

// ------------------------- device-global scratch ---------------------------
__device__ __nv_bfloat16 g_qh[Bm*Hh*Tt*Dd];  // [B,H,T,D] bf16 hi (pre-scaled 1/8)
__device__ __nv_bfloat16 g_ql[Bm*Hh*Tt*Dd];
__device__ __nv_bfloat16 g_kh[Bm*Hh*Tt*Dd];
__device__ __nv_bfloat16 g_kl[Bm*Hh*Tt*Dd];
__device__ __nv_bfloat16 g_vh[Bm*Hh*Tt*Dd];
__device__ __nv_bfloat16 g_vl[Bm*Hh*Tt*Dd];

__device__ __nv_bfloat16 g_xh[Mrows*Cc];
__device__ __nv_bfloat16 g_xl[Mrows*Cc];
__device__ __nv_bfloat16 g_yh[Mrows*Cc];
__device__ __nv_bfloat16 g_yl[Mrows*Cc];
__device__ __nv_bfloat16 g_wh[4*Cc*Cc];
__device__ __nv_bfloat16 g_wl[4*Cc*Cc];

// ---------------------------------------------------------------------------
// single fused split kernel: fp32 -> bf16 hi + lo for x and the 4 weights
// ---------------------------------------------------------------------------
__global__ void split_all(const float* __restrict__ x,
                          const float* __restrict__ Wq, const float* __restrict__ Wk,
                          const float* __restrict__ Wv, const float* __restrict__ Wp)
{
    const int bi = blockIdx.x;
    const int tid = threadIdx.x;
    const float* src;
    __nv_bfloat16 *hi, *lo;
    int i;
    if (bi < 8192) {
        src = x; hi = g_xh; lo = g_xl;
        i = (bi * 256 + tid) * 4;
    } else {
        int r = bi - 8192;
        int which = r >> 10;
        src = (which == 0) ? Wq : (which == 1) ? Wk : (which == 2) ? Wv : Wp;
        hi = g_wh + (size_t)which * Cc * Cc;
        lo = g_wl + (size_t)which * Cc * Cc;
        i = (((r & 1023) * 256) + tid) * 4;
    }

    float4 v = *(const float4*)(src + i);
    __nv_bfloat16 h0 = __float2bfloat16_rn(v.x);
    __nv_bfloat16 h1 = __float2bfloat16_rn(v.y);
    __nv_bfloat16 h2 = __float2bfloat16_rn(v.z);
    __nv_bfloat16 h3 = __float2bfloat16_rn(v.w);
    hi[i+0] = h0; hi[i+1] = h1; hi[i+2] = h2; hi[i+3] = h3;
    lo[i+0] = __float2bfloat16_rn(v.x - __bfloat162float(h0));
    lo[i+1] = __float2bfloat16_rn(v.y - __bfloat162float(h1));
    lo[i+2] = __float2bfloat16_rn(v.z - __bfloat162float(h2));
    lo[i+3] = __float2bfloat16_rn(v.w - __bfloat162float(h3));
}

// ---------------------------------------------------------------------------
// helpers
// ---------------------------------------------------------------------------
__device__ __forceinline__ uint32_t sptr(const void* p)
{ uint32_t a; asm("{ .reg .u64 t; cvta.to.shared.u64 t, %1; cvt.u32.u64 %0, t; }" : "=r"(a) : "l"(p)); return a; }

__device__ __forceinline__ uint32_t pk(float a, float b)
{
    __nv_bfloat162 t = __floats2bfloat162_rn(a, b);
    return *(uint32_t*)&t;
}

__device__ __forceinline__ void mma16816(float* c, const uint32_t* a, const uint32_t* b)
{
    asm volatile(
        "mma.sync.aligned.m16n8k16.row.col.f32.bf16.bf16.f32 "
        "{%0,%1,%2,%3}, {%4,%5,%6,%7}, {%8,%9}, {%0,%1,%2,%3};\n"
        : "+f"(c[0]), "+f"(c[1]), "+f"(c[2]), "+f"(c[3])
        : "r"(a[0]), "r"(a[1]), "r"(a[2]), "r"(a[3]), "r"(b[0]), "r"(b[1]));
}
__device__ __forceinline__ void ldm4(uint32_t* r, uint32_t a)
{
    asm volatile("ldmatrix.sync.aligned.m8n8.x4.shared.b16 {%0,%1,%2,%3}, [%4];"
        : "=r"(r[0]), "=r"(r[1]), "=r"(r[2]), "=r"(r[3]) : "r"(a));
}
__device__ __forceinline__ void ldm4t(uint32_t* r, uint32_t a)
{
    asm volatile("ldmatrix.sync.aligned.m8n8.x4.trans.shared.b16 {%0,%1,%2,%3}, [%4];"
        : "=r"(r[0]), "=r"(r[1]), "=r"(r[2]), "=r"(r[3]) : "r"(a));
}

__device__ __forceinline__ void cpa16(uint32_t dst, const void* src)
{ asm volatile("cp.async.cg.shared.global [%0], [%1], 16;" :: "r"(dst), "l"(src)); }
#define CP_COMMIT() asm volatile("cp.async.commit_group;" ::: "memory")
#define CP_WAIT1()  asm volatile("cp.async.wait_group 1;" ::: "memory")
#define CP_WAIT0()  asm volatile("cp.async.wait_group 0;" ::: "memory")

// ---------------------------------------------------------------------------
// Split-bf16 GEMM, cp.async double-buffered, 2 CTAs/SM. C = A @ W^T + bias.
// CTA tile 128(M) x 128(N), 8 warps (4M x 2N), warp tile 32x64, K-chunk 16.
// fused=1: blockIdx.z selects Wq/Wk/Wv -> split-epilogue to QKV [B,H,T,D].
// fused=0: fp32 linear to outp.
// Dynamic smem: 2 buffers x (A 12288B + B 12288B) = 49152 B.
// ---------------------------------------------------------------------------
#define PITCH 24
#define GBUF 24576
#define GOFF_AH 0
#define GOFF_AL 6144
#define GOFF_BH 12288
#define GOFF_BL 18432

__global__ __launch_bounds__(256, 2) void gemm_db(
    const __nv_bfloat16* __restrict__ Ah, const __nv_bfloat16* __restrict__ Al,
    const __nv_bfloat16* __restrict__ Wh, const __nv_bfloat16* __restrict__ Wl,
    const float* __restrict__ b0, const float* __restrict__ b1,
    const float* __restrict__ b2,
    float* __restrict__ outp, int fused)
{
    extern __shared__ char smem[];
    const uint32_t sb = sptr(smem);

    const int which = blockIdx.z;
    const __nv_bfloat16* __restrict__ Bh = Wh + (size_t)which * Cc * Cc;
    const __nv_bfloat16* __restrict__ Bl = Wl + (size_t)which * Cc * Cc;
    const float* __restrict__ bias = (which == 0) ? b0 : (which == 1) ? b1 : b2;
    const int mode = fused ? which : 3;

    const int tid  = threadIdx.x;
    const int warp = tid >> 5;
    const int lane = tid & 31;
    const int warpM = warp & 3;       // 4 warps in M (32 rows each)
    const int warpN = warp >> 2;      // 2 warps in N (64 cols each)
    const int gid = lane >> 2;
    const int tig = lane & 3;

    const int rowBase = blockIdx.y * 128;
    const int colBase = blockIdx.x * 128;

    float acc[2][8][4];
    #pragma unroll
    for (int i = 0; i < 2; i++)
        #pragma unroll
        for (int j = 0; j < 8; j++)
            #pragma unroll
            for (int k = 0; k < 4; k++) acc[i][j][k] = 0.0f;

    // chunk loader: 1024 cp.async of 16B (A 512 + B 512)
    auto load_chunk = [&](int s, int buf) {
        const int k0 = s * 16;
        const uint32_t bb = sb + buf * GBUF;
        #pragma unroll
        for (int it = 0; it < 2; it++) {
            int fa = tid + it * 256;              // 0..511
            int mat  = fa >> 8;
            int r    = (fa & 255) >> 1;
            int part = fa & 1;
            const __nv_bfloat16* src = mat ? Al : Ah;
            uint32_t dst = bb + (mat ? GOFF_AL : GOFF_AH) + (r * PITCH + part * 8) * 2;
            cpa16(dst, src + (size_t)(rowBase + r) * Cc + k0 + part * 8);
        }
        #pragma unroll
        for (int it = 0; it < 2; it++) {
            int fb = tid + it * 256;              // 0..511
            int mat  = fb >> 8;
            int r    = (fb & 255) >> 1;
            int part = fb & 1;
            const __nv_bfloat16* src = mat ? Bl : Bh;
            uint32_t dst = bb + (mat ? GOFF_BL : GOFF_BH) + (r * PITCH + part * 8) * 2;
            cpa16(dst, src + (size_t)(colBase + r) * Cc + k0 + part * 8);
        }
    };

    load_chunk(0, 0);
    CP_COMMIT();

    for (int s = 0; s < Cc / 16; s++) {
        if (s + 1 < Cc / 16) {
            load_chunk(s + 1, (s + 1) & 1);
            CP_COMMIT();
            CP_WAIT1();
        } else {
            CP_WAIT0();
        }
        __syncthreads();

        const char* bb = smem + (s & 1) * GBUF;
        const __nv_bfloat16* sAh = (const __nv_bfloat16*)(bb + GOFF_AH);
        const __nv_bfloat16* sAl = (const __nv_bfloat16*)(bb + GOFF_AL);
        const __nv_bfloat16* sBh = (const __nv_bfloat16*)(bb + GOFF_BH);
        const __nv_bfloat16* sBl = (const __nv_bfloat16*)(bb + GOFF_BL);

        uint32_t bhf[8][2], blf[8][2];
        #pragma unroll
        for (int ni = 0; ni < 8; ni++) {
            int n = warpN * 64 + ni * 8 + gid;
            bhf[ni][0] = *(const uint32_t*)(sBh + n * PITCH + tig * 2);
            bhf[ni][1] = *(const uint32_t*)(sBh + n * PITCH + tig * 2 + 8);
            blf[ni][0] = *(const uint32_t*)(sBl + n * PITCH + tig * 2);
            blf[ni][1] = *(const uint32_t*)(sBl + n * PITCH + tig * 2 + 8);
        }

        #pragma unroll
        for (int mi = 0; mi < 2; mi++) {
            int r0 = warpM * 32 + mi * 16 + gid;
            uint32_t ah[4], al[4];
            ah[0] = *(const uint32_t*)(sAh + r0 * PITCH + tig * 2);
            ah[1] = *(const uint32_t*)(sAh + (r0 + 8) * PITCH + tig * 2);
            ah[2] = *(const uint32_t*)(sAh + r0 * PITCH + tig * 2 + 8);
            ah[3] = *(const uint32_t*)(sAh + (r0 + 8) * PITCH + tig * 2 + 8);
            al[0] = *(const uint32_t*)(sAl + r0 * PITCH + tig * 2);
            al[1] = *(const uint32_t*)(sAl + (r0 + 8) * PITCH + tig * 2);
            al[2] = *(const uint32_t*)(sAl + r0 * PITCH + tig * 2 + 8);
            al[3] = *(const uint32_t*)(sAl + (r0 + 8) * PITCH + tig * 2 + 8);

            #pragma unroll
            for (int ni = 0; ni < 8; ni++) {
                mma16816(acc[mi][ni], ah, bhf[ni]);
                mma16816(acc[mi][ni], ah, blf[ni]);
                mma16816(acc[mi][ni], al, bhf[ni]);
            }
        }
        __syncthreads();
    }

    // ---- epilogue ----
    if (mode == 3) {
        #pragma unroll
        for (int mi = 0; mi < 2; mi++) {
            #pragma unroll
            for (int ni = 0; ni < 8; ni++) {
                int m0 = rowBase + warpM * 32 + mi * 16 + gid;
                int n0 = colBase + warpN * 64 + ni * 8 + tig * 2;
                #pragma unroll
                for (int e = 0; e < 4; e++) {
                    int m = m0 + ((e >> 1) ? 8 : 0);
                    int n = n0 + (e & 1);
                    outp[(size_t)m * Cc + n] = acc[mi][ni][e] + bias[n];
                }
            }
        }
    } else {
        __nv_bfloat16* dh = (mode == 0) ? g_qh : (mode == 1) ? g_kh : g_vh;
        __nv_bfloat16* dl = (mode == 0) ? g_ql : (mode == 1) ? g_kl : g_vl;
        const float sc = (mode == 0) ? 0.125f : 1.0f;

        #pragma unroll
        for (int mi = 0; mi < 2; mi++) {
            #pragma unroll
            for (int ni = 0; ni < 8; ni++) {
                int m0 = rowBase + warpM * 32 + mi * 16 + gid;
                int n0 = colBase + warpN * 64 + ni * 8 + tig * 2;
                #pragma unroll
                for (int half = 0; half < 2; half++) {
                    int m = m0 + half * 8;
                    float v0 = (acc[mi][ni][half*2+0] + bias[n0])   * sc;
                    float v1 = (acc[mi][ni][half*2+1] + bias[n0+1]) * sc;
                    __nv_bfloat16 h0 = __float2bfloat16_rn(v0);
                    __nv_bfloat16 h1 = __float2bfloat16_rn(v1);
                    int b = m >> 11, t = m & 2047;
                    int h = n0 >> 6, d = n0 & 63;
                    size_t off = (((size_t)(b * Hh + h)) * Tt + t) * Dd + d;
                    __nv_bfloat162 hp; hp.x = h0; hp.y = h1;
                    *(uint32_t*)(dh + off) = *(uint32_t*)&hp;
                    *(uint32_t*)(dl + off) = pk(v0 - __bfloat162float(h0),
                                                v1 - __bfloat162float(h1));
                }
            }
        }
    }
}

// ---------------------------------------------------------------------------
// Flash attention on tensor cores, split-bf16, causal, cp.async double-buffered.
// (unchanged from R7 — proven at 1223us)
// ---------------------------------------------------------------------------
#define ABUFSZ 36864
#define ATT_ARR (64*72*2)     // 9216 B per array

__global__ __launch_bounds__(256, 1) void attn_mma()
{
    extern __shared__ char sm[];
    const uint32_t sbase = sptr(sm);

    const int bh = blockIdx.y;
    const int qblk = (int)gridDim.x - 1 - (int)blockIdx.x;
    const int tid = threadIdx.x;
    const int warp = tid >> 5;
    const int lane = tid & 31;
    const int g = lane >> 2;
    const int tig = lane & 3;

    const size_t base = (size_t)bh * Tt * Dd;

    // ---- stage Q tile into buf0, build A-fragments ----
    {
        __nv_bfloat16* sQh = (__nv_bfloat16*)sm;
        __nv_bfloat16* sQl = sQh + 128*72;
        #pragma unroll
        for (int it = 0; it < 4; it++) {
            int idx = tid + it * 256;
            int r = idx >> 3, c8 = (idx & 7) * 8;
            size_t goff = base + (size_t)(qblk*128 + r) * Dd + c8;
            *(uint4*)(sQh + r*72 + c8) = *(const uint4*)(g_qh + goff);
            *(uint4*)(sQl + r*72 + c8) = *(const uint4*)(g_ql + goff);
        }
    }
    __syncthreads();

    uint32_t qfh[4][4], qfl[4][4];
    {
        __nv_bfloat16* sQh = (__nv_bfloat16*)sm;
        __nv_bfloat16* sQl = sQh + 128*72;
        int row = warp*16 + (lane & 15);
        #pragma unroll
        for (int kt = 0; kt < 4; kt++) {
            int col = kt*16 + (lane >> 4) * 8;
            ldm4(qfh[kt], sptr(sQh + row*72 + col));
            ldm4(qfl[kt], sptr(sQl + row*72 + col));
        }
    }
    __syncthreads();

    float o[8][4];
    #pragma unroll
    for (int i = 0; i < 8; i++)
        #pragma unroll
        for (int j = 0; j < 4; j++) o[i][j] = 0.0f;

    float mA = -INFINITY, mB = -INFINITY, lA = 0.0f, lB = 0.0f;
    const int wr0 = qblk*128 + warp*16;
    const int ntiles = 2*qblk + 2;

    auto load_kv = [&](int kb, int buf) {
        const uint32_t bb = sbase + buf * ABUFSZ;
        #pragma unroll
        for (int it = 0; it < 2; it++) {
            int idx = tid + it * 256;
            int r = idx >> 3, c8 = (idx & 7) * 8;
            size_t goff = base + (size_t)(kb + r) * Dd + c8;
            uint32_t so = (r*72 + c8) * 2;
            cpa16(bb + 0*ATT_ARR + so, g_kh + goff);
            cpa16(bb + 1*ATT_ARR + so, g_kl + goff);
            cpa16(bb + 2*ATT_ARR + so, g_vh + goff);
            cpa16(bb + 3*ATT_ARR + so, g_vl + goff);
        }
    };

    load_kv(0, 0);
    CP_COMMIT();

    for (int ti = 0; ti < ntiles; ti++) {
        const int kb = ti * 64;
        if (ti + 1 < ntiles) {
            load_kv(kb + 64, (ti + 1) & 1);
            CP_COMMIT();
            CP_WAIT1();
        } else {
            CP_WAIT0();
        }
        __syncthreads();

        const char* bb = sm + (ti & 1) * ABUFSZ;
        const __nv_bfloat16* sKh = (const __nv_bfloat16*)(bb + 0*ATT_ARR);
        const __nv_bfloat16* sKl = (const __nv_bfloat16*)(bb + 1*ATT_ARR);
        const __nv_bfloat16* sVh = (const __nv_bfloat16*)(bb + 2*ATT_ARR);
        const __nv_bfloat16* sVl = (const __nv_bfloat16*)(bb + 3*ATT_ARR);

        // ---- S = Q K^T (3-term split) ----
        float s[8][4];
        #pragma unroll
        for (int i = 0; i < 8; i++)
            #pragma unroll
            for (int j = 0; j < 4; j++) s[i][j] = 0.0f;

        #pragma unroll
        for (int kt = 0; kt < 4; kt++) {
            uint32_t kh4[4][4], kl4[4][4];
            #pragma unroll
            for (int i = 0; i < 4; i++) {
                int row = i*16 + (lane & 15);
                int col = kt*16 + (lane >> 4) * 8;
                ldm4(kh4[i], sptr(sKh + row*72 + col));
                ldm4(kl4[i], sptr(sKl + row*72 + col));
            }
            #pragma unroll
            for (int i = 0; i < 4; i++) {
                uint32_t b0h[2] = {kh4[i][0], kh4[i][2]};
                uint32_t b1h[2] = {kh4[i][1], kh4[i][3]};
                uint32_t b0l[2] = {kl4[i][0], kl4[i][2]};
                uint32_t b1l[2] = {kl4[i][1], kl4[i][3]};
                mma16816(s[2*i],   qfh[kt], b0h);
                mma16816(s[2*i],   qfh[kt], b0l);
                mma16816(s[2*i],   qfl[kt], b0h);
                mma16816(s[2*i+1], qfh[kt], b1h);
                mma16816(s[2*i+1], qfh[kt], b1l);
                mma16816(s[2*i+1], qfl[kt], b1h);
            }
        }

        // ---- causal mask ----
        if (kb + 64 > wr0) {
            int rA = wr0 + g, rB = rA + 8;
            #pragma unroll
            for (int nt = 0; nt < 8; nt++) {
                int c0 = kb + nt*8 + tig*2;
                if (c0     > rA) s[nt][0] = -INFINITY;
                if (c0 + 1 > rA) s[nt][1] = -INFINITY;
                if (c0     > rB) s[nt][2] = -INFINITY;
                if (c0 + 1 > rB) s[nt][3] = -INFINITY;
            }
        }

        // ---- online softmax ----
        float ma = -INFINITY, mb = -INFINITY;
        #pragma unroll
        for (int nt = 0; nt < 8; nt++) {
            ma = fmaxf(ma, fmaxf(s[nt][0], s[nt][1]));
            mb = fmaxf(mb, fmaxf(s[nt][2], s[nt][3]));
        }
        ma = fmaxf(ma, __shfl_xor_sync(0xffffffff, ma, 1));
        ma = fmaxf(ma, __shfl_xor_sync(0xffffffff, ma, 2));
        mb = fmaxf(mb, __shfl_xor_sync(0xffffffff, mb, 1));
        mb = fmaxf(mb, __shfl_xor_sync(0xffffffff, mb, 2));

        float nmA = fmaxf(mA, ma), nmB = fmaxf(mB, mb);
        float cA = __expf(mA - nmA), cB = __expf(mB - nmB);
        mA = nmA; mB = nmB;
        lA *= cA; lB *= cB;
        #pragma unroll
        for (int nt = 0; nt < 8; nt++) {
            o[nt][0] *= cA; o[nt][1] *= cA;
            o[nt][2] *= cB; o[nt][3] *= cB;
        }

        uint32_t pah[4][4], pal[4][4];
        float suA = 0.0f, suB = 0.0f;
        #pragma unroll
        for (int nt = 0; nt < 8; nt++) {
            float p0 = __expf(s[nt][0] - nmA);
            float p1 = __expf(s[nt][1] - nmA);
            float p2 = __expf(s[nt][2] - nmB);
            float p3 = __expf(s[nt][3] - nmB);
            suA += p0 + p1; suB += p2 + p3;
            __nv_bfloat16 h0 = __float2bfloat16_rn(p0);
            __nv_bfloat16 h1 = __float2bfloat16_rn(p1);
            __nv_bfloat16 h2 = __float2bfloat16_rn(p2);
            __nv_bfloat16 h3 = __float2bfloat16_rn(p3);
            int kt = nt >> 1, hi2 = (nt & 1) * 2;
            __nv_bfloat162 t01; t01.x = h0; t01.y = h1;
            __nv_bfloat162 t23; t23.x = h2; t23.y = h3;
            pah[kt][hi2 + 0] = *(uint32_t*)&t01;
            pah[kt][hi2 + 1] = *(uint32_t*)&t23;
            pal[kt][hi2 + 0] = pk(p0 - __bfloat162float(h0), p1 - __bfloat162float(h1));
            pal[kt][hi2 + 1] = pk(p2 - __bfloat162float(h2), p3 - __bfloat162float(h3));
        }
        suA += __shfl_xor_sync(0xffffffff, suA, 1);
        suA += __shfl_xor_sync(0xffffffff, suA, 2);
        suB += __shfl_xor_sync(0xffffffff, suB, 1);
        suB += __shfl_xor_sync(0xffffffff, suB, 2);
        lA += suA; lB += suB;

        // ---- O += P V (3-term split) ----
        #pragma unroll
        for (int kt = 0; kt < 4; kt++) {
            uint32_t vh4[4][4], vl4[4][4];
            #pragma unroll
            for (int j = 0; j < 4; j++) {
                int row = kt*16 + (lane & 15);
                int col = j*16 + (lane >> 4) * 8;
                ldm4t(vh4[j], sptr(sVh + row*72 + col));
                ldm4t(vl4[j], sptr(sVl + row*72 + col));
            }
            #pragma unroll
            for (int j = 0; j < 4; j++) {
                uint32_t b0h[2] = {vh4[j][0], vh4[j][1]};
                uint32_t b1h[2] = {vh4[j][2], vh4[j][3]};
                uint32_t b0l[2] = {vl4[j][0], vl4[j][1]};
                uint32_t b1l[2] = {vl4[j][2], vl4[j][3]};
                mma16816(o[2*j],   pah[kt], b0h);
                mma16816(o[2*j],   pah[kt], b0l);
                mma16816(o[2*j],   pal[kt], b0h);
                mma16816(o[2*j+1], pah[kt], b1h);
                mma16816(o[2*j+1], pah[kt], b1l);
                mma16816(o[2*j+1], pal[kt], b1h);
            }
        }
        __syncthreads();
    }

    // ---- epilogue: normalize, split to bf16 hi/lo, write [B,T,C] ----
    const float iA = 1.0f / lA, iB = 1.0f / lB;
    const int b = bh >> 4, h = bh & 15;
    const int rA = qblk*128 + warp*16 + g;
    const size_t offA = ((size_t)(b * Tt + rA)) * Cc + h * 64;
    const size_t offB = offA + (size_t)8 * Cc;

    #pragma unroll
    for (int nt = 0; nt < 8; nt++) {
        int c = nt*8 + tig*2;
        float y0 = o[nt][0] * iA, y1 = o[nt][1] * iA;
        float y2 = o[nt][2] * iB, y3 = o[nt][3] * iB;
        __nv_bfloat16 h0 = __float2bfloat16_rn(y0);
        __nv_bfloat16 h1 = __float2bfloat16_rn(y1);
        __nv_bfloat16 h2 = __float2bfloat16_rn(y2);
        __nv_bfloat16 h3 = __float2bfloat16_rn(y3);
        __nv_bfloat162 tA; tA.x = h0; tA.y = h1;
        __nv_bfloat162 tB; tB.x = h2; tB.y = h3;
        *(uint32_t*)(g_yh + offA + c) = *(uint32_t*)&tA;
        *(uint32_t*)(g_yh + offB + c) = *(uint32_t*)&tB;
        *(uint32_t*)(g_yl + offA + c) = pk(y0 - __bfloat162float(h0), y1 - __bfloat162float(h1));
        *(uint32_t*)(g_yl + offB + c) = pk(y2 - __bfloat162float(h2), y3 - __bfloat162float(h3));
    }
}

// ---------------------------------------------------------------------------
extern "C" void kernel_launch(void* const* d_in, const int* in_sizes, int n_in,
                              void* d_out, int out_size)
{
    const float* x  = (const float*)d_in[0];
    const float* Wq = (const float*)d_in[1];
    const float* bq = (const float*)d_in[2];
    const float* Wk = (const float*)d_in[3];
    const float* bk = (const float*)d_in[4];
    const float* Wv = (const float*)d_in[5];
    const float* bv = (const float*)d_in[6];
    const float* Wp = (const float*)d_in[7];
    const float* bp = (const float*)d_in[8];
    float* out = (float*)d_out;

    __nv_bfloat16 *xh, *xl, *yh, *yl, *wh, *wl;
    cudaGetSymbolAddress((void**)&xh, g_xh);
    cudaGetSymbolAddress((void**)&xl, g_xl);
    cudaGetSymbolAddress((void**)&yh, g_yh);
    cudaGetSymbolAddress((void**)&yl, g_yl);
    cudaGetSymbolAddress((void**)&wh, g_wh);
    cudaGetSymbolAddress((void**)&wl, g_wl);

    cudaFuncSetAttribute(gemm_db, cudaFuncAttributeMaxDynamicSharedMemorySize, 2*GBUF);
    cudaFuncSetAttribute(attn_mma, cudaFuncAttributeMaxDynamicSharedMemorySize, 2*ABUFSZ);

    // all splits in one launch
    split_all<<<8192 + 4096, 256>>>(x, Wq, Wk, Wv, Wp);

    // fused QKV: one launch, z = 3
    const int nw = Cc * Cc;
    dim3 gQKV(Cc / 128, Mrows / 128, 3);     // 8 x 64 x 3
    gemm_db<<<gQKV, 256, 2*GBUF>>>(xh, xl, wh, wl, bq, bk, bv, nullptr, 1);

    dim3 gA(Tt / 128, Bm * Hh);
    attn_mma<<<gA, 256, 2*ABUFSZ>>>();

    // out projection
    dim3 gO(Cc / 128, Mrows / 128, 1);       // 8 x 64
    gemm_db<<<gO, 256, 2*GBUF>>>(yh, yl, wh + 3*nw, wl + 3*nw, bp, bp, bp, out, 0);
}

// round 10
// speedup vs baseline: 1.2852x; 1.0550x over previous
#include <cuda_runtime.h>
#include <cuda_bf16.h>
#include <math.h>
#include <stdint.h>

#define Bm 4
#define Tt 2048
#define Cc 1024
#define Hh 16
#define Dd 64
#define Mrows (Bm*Tt)   // 8192

// ------------------------- device-global scratch ---------------------------
__device__ __nv_bfloat16 g_qh[Bm*Hh*Tt*Dd];  // [B,H,T,D] bf16 hi (pre-scaled 1/8)
__device__ __nv_bfloat16 g_ql[Bm*Hh*Tt*Dd];
__device__ __nv_bfloat16 g_kh[Bm*Hh*Tt*Dd];
__device__ __nv_bfloat16 g_kl[Bm*Hh*Tt*Dd];
__device__ __nv_bfloat16 g_vh[Bm*Hh*Tt*Dd];
__device__ __nv_bfloat16 g_vl[Bm*Hh*Tt*Dd];

__device__ __nv_bfloat16 g_xh[Mrows*Cc];
__device__ __nv_bfloat16 g_xl[Mrows*Cc];
__device__ __nv_bfloat16 g_yh[Mrows*Cc];
__device__ __nv_bfloat16 g_yl[Mrows*Cc];
__device__ __nv_bfloat16 g_wh[4*Cc*Cc];
__device__ __nv_bfloat16 g_wl[4*Cc*Cc];

// ---------------------------------------------------------------------------
// single fused split kernel: fp32 -> bf16 hi + lo for x and the 4 weights
// ---------------------------------------------------------------------------
__global__ void split_all(const float* __restrict__ x,
                          const float* __restrict__ Wq, const float* __restrict__ Wk,
                          const float* __restrict__ Wv, const float* __restrict__ Wp)
{
    const int bi = blockIdx.x;
    const int tid = threadIdx.x;
    const float* src;
    __nv_bfloat16 *hi, *lo;
    int i;
    if (bi < 8192) {
        src = x; hi = g_xh; lo = g_xl;
        i = (bi * 256 + tid) * 4;
    } else {
        int r = bi - 8192;
        int which = r >> 10;
        src = (which == 0) ? Wq : (which == 1) ? Wk : (which == 2) ? Wv : Wp;
        hi = g_wh + (size_t)which * Cc * Cc;
        lo = g_wl + (size_t)which * Cc * Cc;
        i = (((r & 1023) * 256) + tid) * 4;
    }

    float4 v = *(const float4*)(src + i);
    __nv_bfloat16 h0 = __float2bfloat16_rn(v.x);
    __nv_bfloat16 h1 = __float2bfloat16_rn(v.y);
    __nv_bfloat16 h2 = __float2bfloat16_rn(v.z);
    __nv_bfloat16 h3 = __float2bfloat16_rn(v.w);
    hi[i+0] = h0; hi[i+1] = h1; hi[i+2] = h2; hi[i+3] = h3;
    lo[i+0] = __float2bfloat16_rn(v.x - __bfloat162float(h0));
    lo[i+1] = __float2bfloat16_rn(v.y - __bfloat162float(h1));
    lo[i+2] = __float2bfloat16_rn(v.z - __bfloat162float(h2));
    lo[i+3] = __float2bfloat16_rn(v.w - __bfloat162float(h3));
}

// ---------------------------------------------------------------------------
// helpers
// ---------------------------------------------------------------------------
__device__ __forceinline__ uint32_t sptr(const void* p)
{ uint32_t a; asm("{ .reg .u64 t; cvta.to.shared.u64 t, %1; cvt.u32.u64 %0, t; }" : "=r"(a) : "l"(p)); return a; }

__device__ __forceinline__ uint32_t pk(float a, float b)
{
    __nv_bfloat162 t = __floats2bfloat162_rn(a, b);
    return *(uint32_t*)&t;
}

__device__ __forceinline__ void mma16816(float* c, const uint32_t* a, const uint32_t* b)
{
    asm volatile(
        "mma.sync.aligned.m16n8k16.row.col.f32.bf16.bf16.f32 "
        "{%0,%1,%2,%3}, {%4,%5,%6,%7}, {%8,%9}, {%0,%1,%2,%3};\n"
        : "+f"(c[0]), "+f"(c[1]), "+f"(c[2]), "+f"(c[3])
        : "r"(a[0]), "r"(a[1]), "r"(a[2]), "r"(a[3]), "r"(b[0]), "r"(b[1]));
}
__device__ __forceinline__ void ldm4(uint32_t* r, uint32_t a)
{
    asm volatile("ldmatrix.sync.aligned.m8n8.x4.shared.b16 {%0,%1,%2,%3}, [%4];"
        : "=r"(r[0]), "=r"(r[1]), "=r"(r[2]), "=r"(r[3]) : "r"(a));
}
__device__ __forceinline__ void ldm4t(uint32_t* r, uint32_t a)
{
    asm volatile("ldmatrix.sync.aligned.m8n8.x4.trans.shared.b16 {%0,%1,%2,%3}, [%4];"
        : "=r"(r[0]), "=r"(r[1]), "=r"(r[2]), "=r"(r[3]) : "r"(a));
}

__device__ __forceinline__ void cpa16(uint32_t dst, const void* src)
{ asm volatile("cp.async.cg.shared.global [%0], [%1], 16;" :: "r"(dst), "l"(src)); }
#define CP_COMMIT() asm volatile("cp.async.commit_group;" ::: "memory")
#define CP_WAIT0()  asm volatile("cp.async.wait_group 0;" ::: "memory")

// ---------------------------------------------------------------------------
// Split-bf16 GEMM, K-stage 32, single-bar pipeline, ldmatrix frags, 2 CTAs/SM.
// C = A @ W^T + bias. CTA tile 128(M) x 128(N), 8 warps (4M x 2N), warp 32x64.
// Stage rows: 64B data @ 80B pitch (conflict-free ldmatrix).
// fused=1: blockIdx.z selects Wq/Wk/Wv -> split-epilogue to QKV [B,H,T,D].
// fused=0: fp32 linear to outp.
// Dynamic smem: 2 stages x 40960 = 81920 B -> 2 CTAs/SM (160KB).
// ---------------------------------------------------------------------------
#define PE   40              // pitch in bf16 elements (80 B)
#define STG  40960           // stage bytes (4 arrays x 128 rows x 80 B)
#define G_SMEM (2*STG)

__global__ __launch_bounds__(256, 2) void gemm_db(
    const __nv_bfloat16* __restrict__ Ah, const __nv_bfloat16* __restrict__ Al,
    const __nv_bfloat16* __restrict__ Wh, const __nv_bfloat16* __restrict__ Wl,
    const float* __restrict__ b0, const float* __restrict__ b1,
    const float* __restrict__ b2,
    float* __restrict__ outp, int fused)
{
    extern __shared__ char smem[];
    const uint32_t sb = sptr(smem);

    const int which = blockIdx.z;
    const __nv_bfloat16* __restrict__ Bh = Wh + (size_t)which * Cc * Cc;
    const __nv_bfloat16* __restrict__ Bl = Wl + (size_t)which * Cc * Cc;
    const float* __restrict__ bias = (which == 0) ? b0 : (which == 1) ? b1 : b2;
    const int mode = fused ? which : 3;

    const int tid  = threadIdx.x;
    const int warp = tid >> 5;
    const int lane = tid & 31;
    const int warpM = warp & 3;       // 4 warps in M (32 rows each)
    const int warpN = warp >> 2;      // 2 warps in N (64 cols each)
    const int gid = lane >> 2;
    const int tig = lane & 3;

    const int rowBase = blockIdx.y * 128;
    const int colBase = blockIdx.x * 128;

    float acc[2][8][4];
    #pragma unroll
    for (int i = 0; i < 2; i++)
        #pragma unroll
        for (int j = 0; j < 8; j++)
            #pragma unroll
            for (int k = 0; k < 4; k++) acc[i][j][k] = 0.0f;

    // stage loader: 512 rows x 64B = 2048 cp.async of 16B, 8 per thread
    auto issue = [&](int s, int buf) {
        const int k0 = s * 32;
        const uint32_t bb = sb + buf * STG;
        #pragma unroll
        for (int t = 0; t < 8; t++) {
            int idx = tid + t * 256;          // 0..2047
            int row = idx >> 2;               // 0..511
            int part = idx & 3;
            int arr = row >> 7;               // 0:Ah 1:Al 2:Bh 3:Bl
            int r = row & 127;
            const __nv_bfloat16* src =
                (arr == 0) ? Ah : (arr == 1) ? Al : (arr == 2) ? Bh : Bl;
            int grow = (arr < 2) ? (rowBase + r) : (colBase + r);
            cpa16(bb + arr * 10240 + r * 80 + part * 16,
                  src + (size_t)grow * Cc + k0 + part * 8);
        }
    };

    issue(0, 0);
    CP_COMMIT();

    for (int s = 0; s < 32; s++) {
        CP_WAIT0();
        __syncthreads();
        if (s + 1 < 32) { issue(s + 1, (s + 1) & 1); CP_COMMIT(); }

        const char* bb = smem + (s & 1) * STG;
        const __nv_bfloat16* sAh = (const __nv_bfloat16*)(bb + 0);
        const __nv_bfloat16* sAl = (const __nv_bfloat16*)(bb + 10240);
        const __nv_bfloat16* sBh = (const __nv_bfloat16*)(bb + 20480);
        const __nv_bfloat16* sBl = (const __nv_bfloat16*)(bb + 30720);

        #pragma unroll
        for (int kg = 0; kg < 2; kg++) {
            const int colE = kg * 16 + (lane >> 4) * 8;
            const int arow = warpM * 32 + (lane & 15);

            uint32_t ah0[4], ah1[4], al0[4], al1[4];
            ldm4(ah0, sptr(sAh + arow * PE + colE));
            ldm4(ah1, sptr(sAh + (arow + 16) * PE + colE));
            ldm4(al0, sptr(sAl + arow * PE + colE));
            ldm4(al1, sptr(sAl + (arow + 16) * PE + colE));

            #pragma unroll
            for (int grp = 0; grp < 4; grp++) {
                const int brow = warpN * 64 + grp * 16 + (lane & 15);
                uint32_t th[4], tl[4];
                ldm4(th, sptr(sBh + brow * PE + colE));
                ldm4(tl, sptr(sBl + brow * PE + colE));
                uint32_t b0h[2] = {th[0], th[2]};
                uint32_t b1h[2] = {th[1], th[3]};
                uint32_t b0l[2] = {tl[0], tl[2]};
                uint32_t b1l[2] = {tl[1], tl[3]};
                const int n0 = 2 * grp, n1 = 2 * grp + 1;

                mma16816(acc[0][n0], ah0, b0h);
                mma16816(acc[0][n0], ah0, b0l);
                mma16816(acc[0][n0], al0, b0h);
                mma16816(acc[0][n1], ah0, b1h);
                mma16816(acc[0][n1], ah0, b1l);
                mma16816(acc[0][n1], al0, b1h);
                mma16816(acc[1][n0], ah1, b0h);
                mma16816(acc[1][n0], ah1, b0l);
                mma16816(acc[1][n0], al1, b0h);
                mma16816(acc[1][n1], ah1, b1h);
                mma16816(acc[1][n1], ah1, b1l);
                mma16816(acc[1][n1], al1, b1h);
            }
        }
    }

    // ---- epilogue ----
    if (mode == 3) {
        #pragma unroll
        for (int mi = 0; mi < 2; mi++) {
            #pragma unroll
            for (int ni = 0; ni < 8; ni++) {
                int m0 = rowBase + warpM * 32 + mi * 16 + gid;
                int n0 = colBase + warpN * 64 + ni * 8 + tig * 2;
                #pragma unroll
                for (int e = 0; e < 4; e++) {
                    int m = m0 + ((e >> 1) ? 8 : 0);
                    int n = n0 + (e & 1);
                    outp[(size_t)m * Cc + n] = acc[mi][ni][e] + bias[n];
                }
            }
        }
    } else {
        __nv_bfloat16* dh = (mode == 0) ? g_qh : (mode == 1) ? g_kh : g_vh;
        __nv_bfloat16* dl = (mode == 0) ? g_ql : (mode == 1) ? g_kl : g_vl;
        const float sc = (mode == 0) ? 0.125f : 1.0f;

        #pragma unroll
        for (int mi = 0; mi < 2; mi++) {
            #pragma unroll
            for (int ni = 0; ni < 8; ni++) {
                int m0 = rowBase + warpM * 32 + mi * 16 + gid;
                int n0 = colBase + warpN * 64 + ni * 8 + tig * 2;
                #pragma unroll
                for (int half = 0; half < 2; half++) {
                    int m = m0 + half * 8;
                    float v0 = (acc[mi][ni][half*2+0] + bias[n0])   * sc;
                    float v1 = (acc[mi][ni][half*2+1] + bias[n0+1]) * sc;
                    __nv_bfloat16 h0 = __float2bfloat16_rn(v0);
                    __nv_bfloat16 h1 = __float2bfloat16_rn(v1);
                    int b = m >> 11, t = m & 2047;
                    int h = n0 >> 6, d = n0 & 63;
                    size_t off = (((size_t)(b * Hh + h)) * Tt + t) * Dd + d;
                    __nv_bfloat162 hp; hp.x = h0; hp.y = h1;
                    *(uint32_t*)(dh + off) = *(uint32_t*)&hp;
                    *(uint32_t*)(dl + off) = pk(v0 - __bfloat162float(h0),
                                                v1 - __bfloat162float(h1));
                }
            }
        }
    }
}

// ---------------------------------------------------------------------------
// Flash attention, split-bf16, causal, cp.async, single-bar pipeline.
// Grid (16, 64), 256 threads (8 warps x 16 q-rows). K/V tiles of 64 keys.
// ---------------------------------------------------------------------------
#define ABUFSZ 36864
#define ATT_ARR (64*72*2)     // 9216 B per array

__global__ __launch_bounds__(256, 1) void attn_mma()
{
    extern __shared__ char sm[];
    const uint32_t sbase = sptr(sm);

    const int bh = blockIdx.y;
    const int qblk = (int)gridDim.x - 1 - (int)blockIdx.x;
    const int tid = threadIdx.x;
    const int warp = tid >> 5;
    const int lane = tid & 31;
    const int g = lane >> 2;
    const int tig = lane & 3;

    const size_t base = (size_t)bh * Tt * Dd;

    // ---- stage Q tile into buf0, build A-fragments ----
    {
        __nv_bfloat16* sQh = (__nv_bfloat16*)sm;
        __nv_bfloat16* sQl = sQh + 128*72;
        #pragma unroll
        for (int it = 0; it < 4; it++) {
            int idx = tid + it * 256;
            int r = idx >> 3, c8 = (idx & 7) * 8;
            size_t goff = base + (size_t)(qblk*128 + r) * Dd + c8;
            *(uint4*)(sQh + r*72 + c8) = *(const uint4*)(g_qh + goff);
            *(uint4*)(sQl + r*72 + c8) = *(const uint4*)(g_ql + goff);
        }
    }
    __syncthreads();

    uint32_t qfh[4][4], qfl[4][4];
    {
        __nv_bfloat16* sQh = (__nv_bfloat16*)sm;
        __nv_bfloat16* sQl = sQh + 128*72;
        int row = warp*16 + (lane & 15);
        #pragma unroll
        for (int kt = 0; kt < 4; kt++) {
            int col = kt*16 + (lane >> 4) * 8;
            ldm4(qfh[kt], sptr(sQh + row*72 + col));
            ldm4(qfl[kt], sptr(sQl + row*72 + col));
        }
    }
    __syncthreads();

    float o[8][4];
    #pragma unroll
    for (int i = 0; i < 8; i++)
        #pragma unroll
        for (int j = 0; j < 4; j++) o[i][j] = 0.0f;

    float mA = -INFINITY, mB = -INFINITY, lA = 0.0f, lB = 0.0f;
    const int wr0 = qblk*128 + warp*16;
    const int ntiles = 2*qblk + 2;

    auto load_kv = [&](int kb, int buf) {
        const uint32_t bb = sbase + buf * ABUFSZ;
        #pragma unroll
        for (int it = 0; it < 2; it++) {
            int idx = tid + it * 256;
            int r = idx >> 3, c8 = (idx & 7) * 8;
            size_t goff = base + (size_t)(kb + r) * Dd + c8;
            uint32_t so = (r*72 + c8) * 2;
            cpa16(bb + 0*ATT_ARR + so, g_kh + goff);
            cpa16(bb + 1*ATT_ARR + so, g_kl + goff);
            cpa16(bb + 2*ATT_ARR + so, g_vh + goff);
            cpa16(bb + 3*ATT_ARR + so, g_vl + goff);
        }
    };

    load_kv(0, 0);
    CP_COMMIT();

    for (int ti = 0; ti < ntiles; ti++) {
        const int kb = ti * 64;
        CP_WAIT0();
        __syncthreads();
        if (ti + 1 < ntiles) { load_kv(kb + 64, (ti + 1) & 1); CP_COMMIT(); }

        const char* bb = sm + (ti & 1) * ABUFSZ;
        const __nv_bfloat16* sKh = (const __nv_bfloat16*)(bb + 0*ATT_ARR);
        const __nv_bfloat16* sKl = (const __nv_bfloat16*)(bb + 1*ATT_ARR);
        const __nv_bfloat16* sVh = (const __nv_bfloat16*)(bb + 2*ATT_ARR);
        const __nv_bfloat16* sVl = (const __nv_bfloat16*)(bb + 3*ATT_ARR);

        // ---- S = Q K^T (3-term split) ----
        float s[8][4];
        #pragma unroll
        for (int i = 0; i < 8; i++)
            #pragma unroll
            for (int j = 0; j < 4; j++) s[i][j] = 0.0f;

        #pragma unroll
        for (int kt = 0; kt < 4; kt++) {
            uint32_t kh4[4][4], kl4[4][4];
            #pragma unroll
            for (int i = 0; i < 4; i++) {
                int row = i*16 + (lane & 15);
                int col = kt*16 + (lane >> 4) * 8;
                ldm4(kh4[i], sptr(sKh + row*72 + col));
                ldm4(kl4[i], sptr(sKl + row*72 + col));
            }
            #pragma unroll
            for (int i = 0; i < 4; i++) {
                uint32_t b0h[2] = {kh4[i][0], kh4[i][2]};
                uint32_t b1h[2] = {kh4[i][1], kh4[i][3]};
                uint32_t b0l[2] = {kl4[i][0], kl4[i][2]};
                uint32_t b1l[2] = {kl4[i][1], kl4[i][3]};
                mma16816(s[2*i],   qfh[kt], b0h);
                mma16816(s[2*i],   qfh[kt], b0l);
                mma16816(s[2*i],   qfl[kt], b0h);
                mma16816(s[2*i+1], qfh[kt], b1h);
                mma16816(s[2*i+1], qfh[kt], b1l);
                mma16816(s[2*i+1], qfl[kt], b1h);
            }
        }

        // ---- causal mask ----
        if (kb + 64 > wr0) {
            int rA = wr0 + g, rB = rA + 8;
            #pragma unroll
            for (int nt = 0; nt < 8; nt++) {
                int c0 = kb + nt*8 + tig*2;
                if (c0     > rA) s[nt][0] = -INFINITY;
                if (c0 + 1 > rA) s[nt][1] = -INFINITY;
                if (c0     > rB) s[nt][2] = -INFINITY;
                if (c0 + 1 > rB) s[nt][3] = -INFINITY;
            }
        }

        // ---- online softmax ----
        float ma = -INFINITY, mb = -INFINITY;
        #pragma unroll
        for (int nt = 0; nt < 8; nt++) {
            ma = fmaxf(ma, fmaxf(s[nt][0], s[nt][1]));
            mb = fmaxf(mb, fmaxf(s[nt][2], s[nt][3]));
        }
        ma = fmaxf(ma, __shfl_xor_sync(0xffffffff, ma, 1));
        ma = fmaxf(ma, __shfl_xor_sync(0xffffffff, ma, 2));
        mb = fmaxf(mb, __shfl_xor_sync(0xffffffff, mb, 1));
        mb = fmaxf(mb, __shfl_xor_sync(0xffffffff, mb, 2));

        float nmA = fmaxf(mA, ma), nmB = fmaxf(mB, mb);
        float cA = __expf(mA - nmA), cB = __expf(mB - nmB);
        mA = nmA; mB = nmB;
        lA *= cA; lB *= cB;
        #pragma unroll
        for (int nt = 0; nt < 8; nt++) {
            o[nt][0] *= cA; o[nt][1] *= cA;
            o[nt][2] *= cB; o[nt][3] *= cB;
        }

        uint32_t pah[4][4], pal[4][4];
        float suA = 0.0f, suB = 0.0f;
        #pragma unroll
        for (int nt = 0; nt < 8; nt++) {
            float p0 = __expf(s[nt][0] - nmA);
            float p1 = __expf(s[nt][1] - nmA);
            float p2 = __expf(s[nt][2] - nmB);
            float p3 = __expf(s[nt][3] - nmB);
            suA += p0 + p1; suB += p2 + p3;
            __nv_bfloat16 h0 = __float2bfloat16_rn(p0);
            __nv_bfloat16 h1 = __float2bfloat16_rn(p1);
            __nv_bfloat16 h2 = __float2bfloat16_rn(p2);
            __nv_bfloat16 h3 = __float2bfloat16_rn(p3);
            int kt = nt >> 1, hi2 = (nt & 1) * 2;
            __nv_bfloat162 t01; t01.x = h0; t01.y = h1;
            __nv_bfloat162 t23; t23.x = h2; t23.y = h3;
            pah[kt][hi2 + 0] = *(uint32_t*)&t01;
            pah[kt][hi2 + 1] = *(uint32_t*)&t23;
            pal[kt][hi2 + 0] = pk(p0 - __bfloat162float(h0), p1 - __bfloat162float(h1));
            pal[kt][hi2 + 1] = pk(p2 - __bfloat162float(h2), p3 - __bfloat162float(h3));
        }
        suA += __shfl_xor_sync(0xffffffff, suA, 1);
        suA += __shfl_xor_sync(0xffffffff, suA, 2);
        suB += __shfl_xor_sync(0xffffffff, suB, 1);
        suB += __shfl_xor_sync(0xffffffff, suB, 2);
        lA += suA; lB += suB;

        // ---- O += P V (3-term split) ----
        #pragma unroll
        for (int kt = 0; kt < 4; kt++) {
            uint32_t vh4[4][4], vl4[4][4];
            #pragma unroll
            for (int j = 0; j < 4; j++) {
                int row = kt*16 + (lane & 15);
                int col = j*16 + (lane >> 4) * 8;
                ldm4t(vh4[j], sptr(sVh + row*72 + col));
                ldm4t(vl4[j], sptr(sVl + row*72 + col));
            }
            #pragma unroll
            for (int j = 0; j < 4; j++) {
                uint32_t b0h[2] = {vh4[j][0], vh4[j][1]};
                uint32_t b1h[2] = {vh4[j][2], vh4[j][3]};
                uint32_t b0l[2] = {vl4[j][0], vl4[j][1]};
                uint32_t b1l[2] = {vl4[j][2], vl4[j][3]};
                mma16816(o[2*j],   pah[kt], b0h);
                mma16816(o[2*j],   pah[kt], b0l);
                mma16816(o[2*j],   pal[kt], b0h);
                mma16816(o[2*j+1], pah[kt], b1h);
                mma16816(o[2*j+1], pah[kt], b1l);
                mma16816(o[2*j+1], pal[kt], b1h);
            }
        }
    }

    // ---- epilogue: normalize, split to bf16 hi/lo, write [B,T,C] ----
    const float iA = 1.0f / lA, iB = 1.0f / lB;
    const int b = bh >> 4, h = bh & 15;
    const int rA = qblk*128 + warp*16 + g;
    const size_t offA = ((size_t)(b * Tt + rA)) * Cc + h * 64;
    const size_t offB = offA + (size_t)8 * Cc;

    #pragma unroll
    for (int nt = 0; nt < 8; nt++) {
        int c = nt*8 + tig*2;
        float y0 = o[nt][0] * iA, y1 = o[nt][1] * iA;
        float y2 = o[nt][2] * iB, y3 = o[nt][3] * iB;
        __nv_bfloat16 h0 = __float2bfloat16_rn(y0);
        __nv_bfloat16 h1 = __float2bfloat16_rn(y1);
        __nv_bfloat16 h2 = __float2bfloat16_rn(y2);
        __nv_bfloat16 h3 = __float2bfloat16_rn(y3);
        __nv_bfloat162 tA; tA.x = h0; tA.y = h1;
        __nv_bfloat162 tB; tB.x = h2; tB.y = h3;
        *(uint32_t*)(g_yh + offA + c) = *(uint32_t*)&tA;
        *(uint32_t*)(g_yh + offB + c) = *(uint32_t*)&tB;
        *(uint32_t*)(g_yl + offA + c) = pk(y0 - __bfloat162float(h0), y1 - __bfloat162float(h1));
        *(uint32_t*)(g_yl + offB + c) = pk(y2 - __bfloat162float(h2), y3 - __bfloat162float(h3));
    }
}

// ---------------------------------------------------------------------------
extern "C" void kernel_launch(void* const* d_in, const int* in_sizes, int n_in,
                              void* d_out, int out_size)
{
    const float* x  = (const float*)d_in[0];
    const float* Wq = (const float*)d_in[1];
    const float* bq = (const float*)d_in[2];
    const float* Wk = (const float*)d_in[3];
    const float* bk = (const float*)d_in[4];
    const float* Wv = (const float*)d_in[5];
    const float* bv = (const float*)d_in[6];
    const float* Wp = (const float*)d_in[7];
    const float* bp = (const float*)d_in[8];
    float* out = (float*)d_out;

    __nv_bfloat16 *xh, *xl, *yh, *yl, *wh, *wl;
    cudaGetSymbolAddress((void**)&xh, g_xh);
    cudaGetSymbolAddress((void**)&xl, g_xl);
    cudaGetSymbolAddress((void**)&yh, g_yh);
    cudaGetSymbolAddress((void**)&yl, g_yl);
    cudaGetSymbolAddress((void**)&wh, g_wh);
    cudaGetSymbolAddress((void**)&wl, g_wl);

    cudaFuncSetAttribute(gemm_db, cudaFuncAttributeMaxDynamicSharedMemorySize, G_SMEM);
    cudaFuncSetAttribute(attn_mma, cudaFuncAttributeMaxDynamicSharedMemorySize, 2*ABUFSZ);

    // all splits in one launch
    split_all<<<8192 + 4096, 256>>>(x, Wq, Wk, Wv, Wp);

    // fused QKV: one launch, z = 3
    const int nw = Cc * Cc;
    dim3 gQKV(Cc / 128, Mrows / 128, 3);     // 8 x 64 x 3
    gemm_db<<<gQKV, 256, G_SMEM>>>(xh, xl, wh, wl, bq, bk, bv, nullptr, 1);

    dim3 gA(Tt / 128, Bm * Hh);
    attn_mma<<<gA, 256, 2*ABUFSZ>>>();

    // out projection
    dim3 gO(Cc / 128, Mrows / 128, 1);       // 8 x 64
    gemm_db<<<gO, 256, G_SMEM>>>(yh, yl, wh + 3*nw, wl + 3*nw, bp, bp, bp, out, 0);
}

// round 11
// speedup vs baseline: 1.4514x; 1.1293x over previous
#include <cuda_runtime.h>
#include <cuda_fp16.h>
#include <math.h>
#include <stdint.h>

#define Bm 4
#define Tt 2048
#define Cc 1024
#define Hh 16
#define Dd 64
#define Mrows (Bm*Tt)   // 8192

// ------------------------- device-global scratch (fp16 hi/lo) ---------------
__device__ __half g_qh[Bm*Hh*Tt*Dd];  // [B,H,T,D] hi (pre-scaled 1/8)
__device__ __half g_ql[Bm*Hh*Tt*Dd];
__device__ __half g_kh[Bm*Hh*Tt*Dd];
__device__ __half g_kl[Bm*Hh*Tt*Dd];
__device__ __half g_vh[Bm*Hh*Tt*Dd];
__device__ __half g_vl[Bm*Hh*Tt*Dd];

__device__ __half g_xh[Mrows*Cc];
__device__ __half g_xl[Mrows*Cc];
__device__ __half g_yh[Mrows*Cc];      // attention output, fp16 (no lo needed)
__device__ __half g_wh[4*Cc*Cc];
__device__ __half g_wl[4*Cc*Cc];

// ---------------------------------------------------------------------------
// single fused split kernel: fp32 -> fp16 hi + lo for x and the 4 weights
// ---------------------------------------------------------------------------
__global__ void split_all(const float* __restrict__ x,
                          const float* __restrict__ Wq, const float* __restrict__ Wk,
                          const float* __restrict__ Wv, const float* __restrict__ Wp)
{
    const int bi = blockIdx.x;
    const int tid = threadIdx.x;
    const float* src;
    __half *hi, *lo;
    int i;
    if (bi < 8192) {
        src = x; hi = g_xh; lo = g_xl;
        i = (bi * 256 + tid) * 4;
    } else {
        int r = bi - 8192;
        int which = r >> 10;
        src = (which == 0) ? Wq : (which == 1) ? Wk : (which == 2) ? Wv : Wp;
        hi = g_wh + (size_t)which * Cc * Cc;
        lo = g_wl + (size_t)which * Cc * Cc;
        i = (((r & 1023) * 256) + tid) * 4;
    }

    float4 v = *(const float4*)(src + i);
    __half h0 = __float2half_rn(v.x);
    __half h1 = __float2half_rn(v.y);
    __half h2 = __float2half_rn(v.z);
    __half h3 = __float2half_rn(v.w);
    hi[i+0] = h0; hi[i+1] = h1; hi[i+2] = h2; hi[i+3] = h3;
    lo[i+0] = __float2half_rn(v.x - __half2float(h0));
    lo[i+1] = __float2half_rn(v.y - __half2float(h1));
    lo[i+2] = __float2half_rn(v.z - __half2float(h2));
    lo[i+3] = __float2half_rn(v.w - __half2float(h3));
}

// ---------------------------------------------------------------------------
// helpers
// ---------------------------------------------------------------------------
__device__ __forceinline__ uint32_t sptr(const void* p)
{ uint32_t a; asm("{ .reg .u64 t; cvta.to.shared.u64 t, %1; cvt.u32.u64 %0, t; }" : "=r"(a) : "l"(p)); return a; }

__device__ __forceinline__ uint32_t pk(float a, float b)
{
    __half2 t = __floats2half2_rn(a, b);   // a -> low half
    return *(uint32_t*)&t;
}

__device__ __forceinline__ void mma16816(float* c, const uint32_t* a, const uint32_t* b)
{
    asm volatile(
        "mma.sync.aligned.m16n8k16.row.col.f32.f16.f16.f32 "
        "{%0,%1,%2,%3}, {%4,%5,%6,%7}, {%8,%9}, {%0,%1,%2,%3};\n"
        : "+f"(c[0]), "+f"(c[1]), "+f"(c[2]), "+f"(c[3])
        : "r"(a[0]), "r"(a[1]), "r"(a[2]), "r"(a[3]), "r"(b[0]), "r"(b[1]));
}
__device__ __forceinline__ void ldm4(uint32_t* r, uint32_t a)
{
    asm volatile("ldmatrix.sync.aligned.m8n8.x4.shared.b16 {%0,%1,%2,%3}, [%4];"
        : "=r"(r[0]), "=r"(r[1]), "=r"(r[2]), "=r"(r[3]) : "r"(a));
}
__device__ __forceinline__ void ldm4t(uint32_t* r, uint32_t a)
{
    asm volatile("ldmatrix.sync.aligned.m8n8.x4.trans.shared.b16 {%0,%1,%2,%3}, [%4];"
        : "=r"(r[0]), "=r"(r[1]), "=r"(r[2]), "=r"(r[3]) : "r"(a));
}

__device__ __forceinline__ void cpa16(uint32_t dst, const void* src)
{ asm volatile("cp.async.cg.shared.global [%0], [%1], 16;" :: "r"(dst), "l"(src)); }
#define CP_COMMIT() asm volatile("cp.async.commit_group;" ::: "memory")
#define CP_WAIT0()  asm volatile("cp.async.wait_group 0;" ::: "memory")

// ---------------------------------------------------------------------------
// Split-fp16 GEMM, K-stage 32, single-bar pipeline, ldmatrix frags, 2 CTAs/SM.
// C = A @ W^T + bias. CTA tile 128(M) x 128(N), 8 warps (4M x 2N), warp 32x64.
// 3-term (modes 0,1): Ah.Bh + Ah.Bl + Al.Bh.  2-term (modes 2,3): drop Al.Bh.
// fused=1: blockIdx.z selects Wq/Wk/Wv -> split-epilogue to QKV [B,H,T,D].
// fused=0: fp32 linear to outp.
// ---------------------------------------------------------------------------
#define PE   40              // pitch in fp16 elements (80 B)
#define STG  40960           // stage bytes (4 arrays x 128 rows x 80 B)
#define G_SMEM (2*STG)

__global__ __launch_bounds__(256, 2) void gemm_db(
    const __half* __restrict__ Ah, const __half* __restrict__ Al,
    const __half* __restrict__ Wh, const __half* __restrict__ Wl,
    const float* __restrict__ b0, const float* __restrict__ b1,
    const float* __restrict__ b2,
    float* __restrict__ outp, int fused)
{
    extern __shared__ char smem[];
    const uint32_t sb = sptr(smem);

    const int which = blockIdx.z;
    const __half* __restrict__ Bh = Wh + (size_t)which * Cc * Cc;
    const __half* __restrict__ Bl = Wl + (size_t)which * Cc * Cc;
    const float* __restrict__ bias = (which == 0) ? b0 : (which == 1) ? b1 : b2;
    const int mode = fused ? which : 3;
    const bool two = (mode >= 2);        // 2-term: V-proj and out-proj

    const int tid  = threadIdx.x;
    const int warp = tid >> 5;
    const int lane = tid & 31;
    const int warpM = warp & 3;
    const int warpN = warp >> 2;
    const int gid = lane >> 2;
    const int tig = lane & 3;

    const int rowBase = blockIdx.y * 128;
    const int colBase = blockIdx.x * 128;

    float acc[2][8][4];
    #pragma unroll
    for (int i = 0; i < 2; i++)
        #pragma unroll
        for (int j = 0; j < 8; j++)
            #pragma unroll
            for (int k = 0; k < 4; k++) acc[i][j][k] = 0.0f;

    // stage loader: 512 rows x 64B; skip A-lo rows in 2-term modes
    auto issue = [&](int s, int buf) {
        const int k0 = s * 32;
        const uint32_t bb = sb + buf * STG;
        #pragma unroll
        for (int t = 0; t < 8; t++) {
            int idx = tid + t * 256;
            int row = idx >> 2;
            int part = idx & 3;
            int arr = row >> 7;               // 0:Ah 1:Al 2:Bh 3:Bl
            int r = row & 127;
            if (two && arr == 1) continue;    // A-lo unused in 2-term
            const __half* src =
                (arr == 0) ? Ah : (arr == 1) ? Al : (arr == 2) ? Bh : Bl;
            int grow = (arr < 2) ? (rowBase + r) : (colBase + r);
            cpa16(bb + arr * 10240 + r * 80 + part * 16,
                  src + (size_t)grow * Cc + k0 + part * 8);
        }
    };

    issue(0, 0);
    CP_COMMIT();

    for (int s = 0; s < 32; s++) {
        CP_WAIT0();
        __syncthreads();
        if (s + 1 < 32) { issue(s + 1, (s + 1) & 1); CP_COMMIT(); }

        const char* bb = smem + (s & 1) * STG;
        const __half* sAh = (const __half*)(bb + 0);
        const __half* sAl = (const __half*)(bb + 10240);
        const __half* sBh = (const __half*)(bb + 20480);
        const __half* sBl = (const __half*)(bb + 30720);

        #pragma unroll
        for (int kg = 0; kg < 2; kg++) {
            const int colE = kg * 16 + (lane >> 4) * 8;
            const int arow = warpM * 32 + (lane & 15);

            uint32_t ah0[4], ah1[4], al0[4], al1[4];
            ldm4(ah0, sptr(sAh + arow * PE + colE));
            ldm4(ah1, sptr(sAh + (arow + 16) * PE + colE));
            if (!two) {
                ldm4(al0, sptr(sAl + arow * PE + colE));
                ldm4(al1, sptr(sAl + (arow + 16) * PE + colE));
            }

            #pragma unroll
            for (int grp = 0; grp < 4; grp++) {
                const int brow = warpN * 64 + grp * 16 + (lane & 15);
                uint32_t th[4], tl[4];
                ldm4(th, sptr(sBh + brow * PE + colE));
                ldm4(tl, sptr(sBl + brow * PE + colE));
                uint32_t b0h[2] = {th[0], th[2]};
                uint32_t b1h[2] = {th[1], th[3]};
                uint32_t b0l[2] = {tl[0], tl[2]};
                uint32_t b1l[2] = {tl[1], tl[3]};
                const int n0 = 2 * grp, n1 = 2 * grp + 1;

                mma16816(acc[0][n0], ah0, b0h);
                mma16816(acc[0][n0], ah0, b0l);
                mma16816(acc[0][n1], ah0, b1h);
                mma16816(acc[0][n1], ah0, b1l);
                mma16816(acc[1][n0], ah1, b0h);
                mma16816(acc[1][n0], ah1, b0l);
                mma16816(acc[1][n1], ah1, b1h);
                mma16816(acc[1][n1], ah1, b1l);
                if (!two) {
                    mma16816(acc[0][n0], al0, b0h);
                    mma16816(acc[0][n1], al0, b1h);
                    mma16816(acc[1][n0], al1, b0h);
                    mma16816(acc[1][n1], al1, b1h);
                }
            }
        }
    }

    // ---- epilogue ----
    if (mode == 3) {
        #pragma unroll
        for (int mi = 0; mi < 2; mi++) {
            #pragma unroll
            for (int ni = 0; ni < 8; ni++) {
                int m0 = rowBase + warpM * 32 + mi * 16 + gid;
                int n0 = colBase + warpN * 64 + ni * 8 + tig * 2;
                #pragma unroll
                for (int e = 0; e < 4; e++) {
                    int m = m0 + ((e >> 1) ? 8 : 0);
                    int n = n0 + (e & 1);
                    outp[(size_t)m * Cc + n] = acc[mi][ni][e] + bias[n];
                }
            }
        }
    } else {
        __half* dh = (mode == 0) ? g_qh : (mode == 1) ? g_kh : g_vh;
        __half* dl = (mode == 0) ? g_ql : (mode == 1) ? g_kl : g_vl;
        const float sc = (mode == 0) ? 0.125f : 1.0f;

        #pragma unroll
        for (int mi = 0; mi < 2; mi++) {
            #pragma unroll
            for (int ni = 0; ni < 8; ni++) {
                int m0 = rowBase + warpM * 32 + mi * 16 + gid;
                int n0 = colBase + warpN * 64 + ni * 8 + tig * 2;
                #pragma unroll
                for (int half = 0; half < 2; half++) {
                    int m = m0 + half * 8;
                    float v0 = (acc[mi][ni][half*2+0] + bias[n0])   * sc;
                    float v1 = (acc[mi][ni][half*2+1] + bias[n0+1]) * sc;
                    __half h0 = __float2half_rn(v0);
                    __half h1 = __float2half_rn(v1);
                    int b = m >> 11, t = m & 2047;
                    int h = n0 >> 6, d = n0 & 63;
                    size_t off = (((size_t)(b * Hh + h)) * Tt + t) * Dd + d;
                    __half2 hp; hp.x = h0; hp.y = h1;
                    *(uint32_t*)(dh + off) = *(uint32_t*)&hp;
                    *(uint32_t*)(dl + off) = pk(v0 - __half2float(h0),
                                                v1 - __half2float(h1));
                }
            }
        }
    }
}

// ---------------------------------------------------------------------------
// Flash attention, split-fp16, causal, cp.async, single-bar pipeline.
// QK^T: 3-term. PV: 2-term (Ph.Vh + Ph.Vl; P lo dropped).
// Grid (16, 64), 256 threads (8 warps x 16 q-rows). K/V tiles of 64 keys.
// ---------------------------------------------------------------------------
#define ABUFSZ 36864
#define ATT_ARR (64*72*2)     // 9216 B per array

__global__ __launch_bounds__(256, 1) void attn_mma()
{
    extern __shared__ char sm[];
    const uint32_t sbase = sptr(sm);

    const int bh = blockIdx.y;
    const int qblk = (int)gridDim.x - 1 - (int)blockIdx.x;
    const int tid = threadIdx.x;
    const int warp = tid >> 5;
    const int lane = tid & 31;
    const int g = lane >> 2;
    const int tig = lane & 3;

    const size_t base = (size_t)bh * Tt * Dd;

    // ---- stage Q tile into buf0, build A-fragments ----
    {
        __half* sQh = (__half*)sm;
        __half* sQl = sQh + 128*72;
        #pragma unroll
        for (int it = 0; it < 4; it++) {
            int idx = tid + it * 256;
            int r = idx >> 3, c8 = (idx & 7) * 8;
            size_t goff = base + (size_t)(qblk*128 + r) * Dd + c8;
            *(uint4*)(sQh + r*72 + c8) = *(const uint4*)(g_qh + goff);
            *(uint4*)(sQl + r*72 + c8) = *(const uint4*)(g_ql + goff);
        }
    }
    __syncthreads();

    uint32_t qfh[4][4], qfl[4][4];
    {
        __half* sQh = (__half*)sm;
        __half* sQl = sQh + 128*72;
        int row = warp*16 + (lane & 15);
        #pragma unroll
        for (int kt = 0; kt < 4; kt++) {
            int col = kt*16 + (lane >> 4) * 8;
            ldm4(qfh[kt], sptr(sQh + row*72 + col));
            ldm4(qfl[kt], sptr(sQl + row*72 + col));
        }
    }
    __syncthreads();

    float o[8][4];
    #pragma unroll
    for (int i = 0; i < 8; i++)
        #pragma unroll
        for (int j = 0; j < 4; j++) o[i][j] = 0.0f;

    float mA = -INFINITY, mB = -INFINITY, lA = 0.0f, lB = 0.0f;
    const int wr0 = qblk*128 + warp*16;
    const int ntiles = 2*qblk + 2;

    auto load_kv = [&](int kb, int buf) {
        const uint32_t bb = sbase + buf * ABUFSZ;
        #pragma unroll
        for (int it = 0; it < 2; it++) {
            int idx = tid + it * 256;
            int r = idx >> 3, c8 = (idx & 7) * 8;
            size_t goff = base + (size_t)(kb + r) * Dd + c8;
            uint32_t so = (r*72 + c8) * 2;
            cpa16(bb + 0*ATT_ARR + so, g_kh + goff);
            cpa16(bb + 1*ATT_ARR + so, g_kl + goff);
            cpa16(bb + 2*ATT_ARR + so, g_vh + goff);
            cpa16(bb + 3*ATT_ARR + so, g_vl + goff);
        }
    };

    load_kv(0, 0);
    CP_COMMIT();

    for (int ti = 0; ti < ntiles; ti++) {
        const int kb = ti * 64;
        CP_WAIT0();
        __syncthreads();
        if (ti + 1 < ntiles) { load_kv(kb + 64, (ti + 1) & 1); CP_COMMIT(); }

        const char* bb = sm + (ti & 1) * ABUFSZ;
        const __half* sKh = (const __half*)(bb + 0*ATT_ARR);
        const __half* sKl = (const __half*)(bb + 1*ATT_ARR);
        const __half* sVh = (const __half*)(bb + 2*ATT_ARR);
        const __half* sVl = (const __half*)(bb + 3*ATT_ARR);

        // ---- S = Q K^T (3-term split) ----
        float s[8][4];
        #pragma unroll
        for (int i = 0; i < 8; i++)
            #pragma unroll
            for (int j = 0; j < 4; j++) s[i][j] = 0.0f;

        #pragma unroll
        for (int kt = 0; kt < 4; kt++) {
            uint32_t kh4[4][4], kl4[4][4];
            #pragma unroll
            for (int i = 0; i < 4; i++) {
                int row = i*16 + (lane & 15);
                int col = kt*16 + (lane >> 4) * 8;
                ldm4(kh4[i], sptr(sKh + row*72 + col));
                ldm4(kl4[i], sptr(sKl + row*72 + col));
            }
            #pragma unroll
            for (int i = 0; i < 4; i++) {
                uint32_t b0h[2] = {kh4[i][0], kh4[i][2]};
                uint32_t b1h[2] = {kh4[i][1], kh4[i][3]};
                uint32_t b0l[2] = {kl4[i][0], kl4[i][2]};
                uint32_t b1l[2] = {kl4[i][1], kl4[i][3]};
                mma16816(s[2*i],   qfh[kt], b0h);
                mma16816(s[2*i],   qfh[kt], b0l);
                mma16816(s[2*i],   qfl[kt], b0h);
                mma16816(s[2*i+1], qfh[kt], b1h);
                mma16816(s[2*i+1], qfh[kt], b1l);
                mma16816(s[2*i+1], qfl[kt], b1h);
            }
        }

        // ---- causal mask ----
        if (kb + 64 > wr0) {
            int rA = wr0 + g, rB = rA + 8;
            #pragma unroll
            for (int nt = 0; nt < 8; nt++) {
                int c0 = kb + nt*8 + tig*2;
                if (c0     > rA) s[nt][0] = -INFINITY;
                if (c0 + 1 > rA) s[nt][1] = -INFINITY;
                if (c0     > rB) s[nt][2] = -INFINITY;
                if (c0 + 1 > rB) s[nt][3] = -INFINITY;
            }
        }

        // ---- online softmax ----
        float ma = -INFINITY, mb = -INFINITY;
        #pragma unroll
        for (int nt = 0; nt < 8; nt++) {
            ma = fmaxf(ma, fmaxf(s[nt][0], s[nt][1]));
            mb = fmaxf(mb, fmaxf(s[nt][2], s[nt][3]));
        }
        ma = fmaxf(ma, __shfl_xor_sync(0xffffffff, ma, 1));
        ma = fmaxf(ma, __shfl_xor_sync(0xffffffff, ma, 2));
        mb = fmaxf(mb, __shfl_xor_sync(0xffffffff, mb, 1));
        mb = fmaxf(mb, __shfl_xor_sync(0xffffffff, mb, 2));

        float nmA = fmaxf(mA, ma), nmB = fmaxf(mB, mb);
        float cA = __expf(mA - nmA), cB = __expf(mB - nmB);
        mA = nmA; mB = nmB;
        lA *= cA; lB *= cB;
        #pragma unroll
        for (int nt = 0; nt < 8; nt++) {
            o[nt][0] *= cA; o[nt][1] *= cA;
            o[nt][2] *= cB; o[nt][3] *= cB;
        }

        // ---- p = exp(s - m), fp16 (no lo split needed for 2-term PV) ----
        uint32_t pah[4][4];
        float suA = 0.0f, suB = 0.0f;
        #pragma unroll
        for (int nt = 0; nt < 8; nt++) {
            float p0 = __expf(s[nt][0] - nmA);
            float p1 = __expf(s[nt][1] - nmA);
            float p2 = __expf(s[nt][2] - nmB);
            float p3 = __expf(s[nt][3] - nmB);
            suA += p0 + p1; suB += p2 + p3;
            int kt = nt >> 1, hi2 = (nt & 1) * 2;
            pah[kt][hi2 + 0] = pk(p0, p1);
            pah[kt][hi2 + 1] = pk(p2, p3);
        }
        suA += __shfl_xor_sync(0xffffffff, suA, 1);
        suA += __shfl_xor_sync(0xffffffff, suA, 2);
        suB += __shfl_xor_sync(0xffffffff, suB, 1);
        suB += __shfl_xor_sync(0xffffffff, suB, 2);
        lA += suA; lB += suB;

        // ---- O += P V (2-term: Ph.Vh + Ph.Vl) ----
        #pragma unroll
        for (int kt = 0; kt < 4; kt++) {
            uint32_t vh4[4][4], vl4[4][4];
            #pragma unroll
            for (int j = 0; j < 4; j++) {
                int row = kt*16 + (lane & 15);
                int col = j*16 + (lane >> 4) * 8;
                ldm4t(vh4[j], sptr(sVh + row*72 + col));
                ldm4t(vl4[j], sptr(sVl + row*72 + col));
            }
            #pragma unroll
            for (int j = 0; j < 4; j++) {
                uint32_t b0h[2] = {vh4[j][0], vh4[j][1]};
                uint32_t b1h[2] = {vh4[j][2], vh4[j][3]};
                uint32_t b0l[2] = {vl4[j][0], vl4[j][1]};
                uint32_t b1l[2] = {vl4[j][2], vl4[j][3]};
                mma16816(o[2*j],   pah[kt], b0h);
                mma16816(o[2*j],   pah[kt], b0l);
                mma16816(o[2*j+1], pah[kt], b1h);
                mma16816(o[2*j+1], pah[kt], b1l);
            }
        }
    }

    // ---- epilogue: normalize, write y as fp16 (hi only) in [B,T,C] ----
    const float iA = 1.0f / lA, iB = 1.0f / lB;
    const int b = bh >> 4, h = bh & 15;
    const int rA = qblk*128 + warp*16 + g;
    const size_t offA = ((size_t)(b * Tt + rA)) * Cc + h * 64;
    const size_t offB = offA + (size_t)8 * Cc;

    #pragma unroll
    for (int nt = 0; nt < 8; nt++) {
        int c = nt*8 + tig*2;
        *(uint32_t*)(g_yh + offA + c) = pk(o[nt][0] * iA, o[nt][1] * iA);
        *(uint32_t*)(g_yh + offB + c) = pk(o[nt][2] * iB, o[nt][3] * iB);
    }
}

// ---------------------------------------------------------------------------
extern "C" void kernel_launch(void* const* d_in, const int* in_sizes, int n_in,
                              void* d_out, int out_size)
{
    const float* x  = (const float*)d_in[0];
    const float* Wq = (const float*)d_in[1];
    const float* bq = (const float*)d_in[2];
    const float* Wk = (const float*)d_in[3];
    const float* bk = (const float*)d_in[4];
    const float* Wv = (const float*)d_in[5];
    const float* bv = (const float*)d_in[6];
    const float* Wp = (const float*)d_in[7];
    const float* bp = (const float*)d_in[8];
    float* out = (float*)d_out;

    __half *xh, *xl, *yh, *wh, *wl;
    cudaGetSymbolAddress((void**)&xh, g_xh);
    cudaGetSymbolAddress((void**)&xl, g_xl);
    cudaGetSymbolAddress((void**)&yh, g_yh);
    cudaGetSymbolAddress((void**)&wh, g_wh);
    cudaGetSymbolAddress((void**)&wl, g_wl);

    cudaFuncSetAttribute(gemm_db, cudaFuncAttributeMaxDynamicSharedMemorySize, G_SMEM);
    cudaFuncSetAttribute(attn_mma, cudaFuncAttributeMaxDynamicSharedMemorySize, 2*ABUFSZ);

    // all splits in one launch
    split_all<<<8192 + 4096, 256>>>(x, Wq, Wk, Wv, Wp);

    // fused QKV: one launch, z = 3 (Q,K 3-term; V 2-term)
    const int nw = Cc * Cc;
    dim3 gQKV(Cc / 128, Mrows / 128, 3);     // 8 x 64 x 3
    gemm_db<<<gQKV, 256, G_SMEM>>>(xh, xl, wh, wl, bq, bk, bv, nullptr, 1);

    dim3 gA(Tt / 128, Bm * Hh);
    attn_mma<<<gA, 256, 2*ABUFSZ>>>();

    // out projection (2-term; A-lo unused -> pass yh as dummy)
    dim3 gO(Cc / 128, Mrows / 128, 1);       // 8 x 64
    gemm_db<<<gO, 256, G_SMEM>>>(yh, yh, wh + 3*nw, wl + 3*nw, bp, bp, bp, out, 0);
}

// round 13
// speedup vs baseline: 1.8096x; 1.2468x over previous
#include <cuda_runtime.h>
#include <cuda_fp16.h>
#include <math.h>
#include <stdint.h>

#define Bm 4
#define Tt 2048
#define Cc 1024
#define Hh 16
#define Dd 64
#define Mrows (Bm*Tt)   // 8192

// ------------------------- device-global scratch (fp16) ---------------------
__device__ __half g_qh[Bm*Hh*Tt*Dd];  // [B,H,T,D] hi (pre-scaled 1/8), no lo
__device__ __half g_kh[Bm*Hh*Tt*Dd];
__device__ __half g_kl[Bm*Hh*Tt*Dd];
__device__ __half g_vh[Bm*Hh*Tt*Dd];
__device__ __half g_vl[Bm*Hh*Tt*Dd];

__device__ __half g_xh[Mrows*Cc];
__device__ __half g_yh[Mrows*Cc];      // attention output (hi only)
__device__ __half g_wh[4*Cc*Cc];
__device__ __half g_wl[4*Cc*Cc];

// ---------------------------------------------------------------------------
// fused split kernel: x -> fp16 hi only; weights -> fp16 hi + lo
// ---------------------------------------------------------------------------
__global__ void split_all(const float* __restrict__ x,
                          const float* __restrict__ Wq, const float* __restrict__ Wk,
                          const float* __restrict__ Wv, const float* __restrict__ Wp)
{
    const int bi = blockIdx.x;
    const int tid = threadIdx.x;

    if (bi < 8192) {
        int i = (bi * 256 + tid) * 4;
        float4 v = *(const float4*)(x + i);
        __half2 a; a.x = __float2half_rn(v.x); a.y = __float2half_rn(v.y);
        __half2 b; b.x = __float2half_rn(v.z); b.y = __float2half_rn(v.w);
        *(uint32_t*)(g_xh + i)     = *(uint32_t*)&a;
        *(uint32_t*)(g_xh + i + 2) = *(uint32_t*)&b;
        return;
    }

    int r = bi - 8192;
    int which = r >> 10;
    const float* src = (which == 0) ? Wq : (which == 1) ? Wk : (which == 2) ? Wv : Wp;
    __half* hi = g_wh + (size_t)which * Cc * Cc;
    __half* lo = g_wl + (size_t)which * Cc * Cc;
    int i = (((r & 1023) * 256) + tid) * 4;

    float4 v = *(const float4*)(src + i);
    __half h0 = __float2half_rn(v.x);
    __half h1 = __float2half_rn(v.y);
    __half h2 = __float2half_rn(v.z);
    __half h3 = __float2half_rn(v.w);
    hi[i+0] = h0; hi[i+1] = h1; hi[i+2] = h2; hi[i+3] = h3;
    lo[i+0] = __float2half_rn(v.x - __half2float(h0));
    lo[i+1] = __float2half_rn(v.y - __half2float(h1));
    lo[i+2] = __float2half_rn(v.z - __half2float(h2));
    lo[i+3] = __float2half_rn(v.w - __half2float(h3));
}

// ---------------------------------------------------------------------------
// helpers
// ---------------------------------------------------------------------------
__device__ __forceinline__ uint32_t sptr(const void* p)
{ uint32_t a; asm("{ .reg .u64 t; cvta.to.shared.u64 t, %1; cvt.u32.u64 %0, t; }" : "=r"(a) : "l"(p)); return a; }

__device__ __forceinline__ uint32_t pk(float a, float b)
{
    __half2 t = __floats2half2_rn(a, b);   // a -> low half
    return *(uint32_t*)&t;
}

__device__ __forceinline__ void mma16816(float* c, const uint32_t* a, const uint32_t* b)
{
    asm volatile(
        "mma.sync.aligned.m16n8k16.row.col.f32.f16.f16.f32 "
        "{%0,%1,%2,%3}, {%4,%5,%6,%7}, {%8,%9}, {%0,%1,%2,%3};\n"
        : "+f"(c[0]), "+f"(c[1]), "+f"(c[2]), "+f"(c[3])
        : "r"(a[0]), "r"(a[1]), "r"(a[2]), "r"(a[3]), "r"(b[0]), "r"(b[1]));
}
__device__ __forceinline__ void ldm4(uint32_t* r, uint32_t a)
{
    asm volatile("ldmatrix.sync.aligned.m8n8.x4.shared.b16 {%0,%1,%2,%3}, [%4];"
        : "=r"(r[0]), "=r"(r[1]), "=r"(r[2]), "=r"(r[3]) : "r"(a));
}
__device__ __forceinline__ void ldm4t(uint32_t* r, uint32_t a)
{
    asm volatile("ldmatrix.sync.aligned.m8n8.x4.trans.shared.b16 {%0,%1,%2,%3}, [%4];"
        : "=r"(r[0]), "=r"(r[1]), "=r"(r[2]), "=r"(r[3]) : "r"(a));
}

__device__ __forceinline__ void cpa16(uint32_t dst, const void* src)
{ asm volatile("cp.async.cg.shared.global [%0], [%1], 16;" :: "r"(dst), "l"(src)); }
#define CP_COMMIT() asm volatile("cp.async.commit_group;" ::: "memory")
#define CP_WAIT0()  asm volatile("cp.async.wait_group 0;" ::: "memory")

// ---------------------------------------------------------------------------
// 2-term split-fp16 GEMM: C = Ah @ (Wh + Wl)^T + bias.
// K-stage 32, single-bar pipeline, ldmatrix frags, 2 CTAs/SM.
// CTA tile 128(M) x 128(N), 8 warps (4M x 2N), warp 32x64.
// Stage: 3 arrays (Ah, Bh, Bl) x 128 rows x 80B pitch = 30720 B; 2 stages.
// fused=1: blockIdx.z selects Wq/Wk/Wv -> epilogue to QKV [B,H,T,D]
//   (mode 0: Q hi only, scaled 1/8; modes 1,2: hi+lo).
// fused=0: fp32 linear to outp.
// ---------------------------------------------------------------------------
#define PE   40              // pitch in fp16 elements (80 B)
#define STG  30720           // stage bytes (3 arrays x 128 rows x 80 B)
#define G_SMEM (2*STG)

__global__ __launch_bounds__(256, 2) void gemm_db(
    const __half* __restrict__ Ah,
    const __half* __restrict__ Wh, const __half* __restrict__ Wl,
    const float* __restrict__ b0, const float* __restrict__ b1,
    const float* __restrict__ b2,
    float* __restrict__ outp, int fused)
{
    extern __shared__ char smem[];
    const uint32_t sb = sptr(smem);

    const int which = blockIdx.z;
    const __half* __restrict__ Bh = Wh + (size_t)which * Cc * Cc;
    const __half* __restrict__ Bl = Wl + (size_t)which * Cc * Cc;
    const float* __restrict__ bias = (which == 0) ? b0 : (which == 1) ? b1 : b2;
    const int mode = fused ? which : 3;

    const int tid  = threadIdx.x;
    const int warp = tid >> 5;
    const int lane = tid & 31;
    const int warpM = warp & 3;
    const int warpN = warp >> 2;
    const int gid = lane >> 2;
    const int tig = lane & 3;

    const int rowBase = blockIdx.y * 128;
    const int colBase = blockIdx.x * 128;

    float acc[2][8][4];
    #pragma unroll
    for (int i = 0; i < 2; i++)
        #pragma unroll
        for (int j = 0; j < 8; j++)
            #pragma unroll
            for (int k = 0; k < 4; k++) acc[i][j][k] = 0.0f;

    // stage loader: 384 rows x 64B = 1536 cp.async of 16B, 6 per thread
    auto issue = [&](int s, int buf) {
        const int k0 = s * 32;
        const uint32_t bb = sb + buf * STG;
        #pragma unroll
        for (int t = 0; t < 6; t++) {
            int idx = tid + t * 256;          // 0..1535
            int row = idx >> 2;               // 0..383
            int part = idx & 3;
            int arr = row >> 7;               // 0:Ah 1:Bh 2:Bl
            int r = row & 127;
            const __half* src = (arr == 0) ? Ah : (arr == 1) ? Bh : Bl;
            int grow = (arr == 0) ? (rowBase + r) : (colBase + r);
            cpa16(bb + arr * 10240 + r * 80 + part * 16,
                  src + (size_t)grow * Cc + k0 + part * 8);
        }
    };

    issue(0, 0);
    CP_COMMIT();

    for (int s = 0; s < 32; s++) {
        CP_WAIT0();
        __syncthreads();
        if (s + 1 < 32) { issue(s + 1, (s + 1) & 1); CP_COMMIT(); }

        const char* bb = smem + (s & 1) * STG;
        const __half* sAh = (const __half*)(bb + 0);
        const __half* sBh = (const __half*)(bb + 10240);
        const __half* sBl = (const __half*)(bb + 20480);

        #pragma unroll
        for (int kg = 0; kg < 2; kg++) {
            const int colE = kg * 16 + (lane >> 4) * 8;
            const int arow = warpM * 32 + (lane & 15);

            uint32_t ah0[4], ah1[4];
            ldm4(ah0, sptr(sAh + arow * PE + colE));
            ldm4(ah1, sptr(sAh + (arow + 16) * PE + colE));

            #pragma unroll
            for (int grp = 0; grp < 4; grp++) {
                const int brow = warpN * 64 + grp * 16 + (lane & 15);
                uint32_t th[4], tl[4];
                ldm4(th, sptr(sBh + brow * PE + colE));
                ldm4(tl, sptr(sBl + brow * PE + colE));
                uint32_t b0h[2] = {th[0], th[2]};
                uint32_t b1h[2] = {th[1], th[3]};
                uint32_t b0l[2] = {tl[0], tl[2]};
                uint32_t b1l[2] = {tl[1], tl[3]};
                const int n0 = 2 * grp, n1 = 2 * grp + 1;

                mma16816(acc[0][n0], ah0, b0h);
                mma16816(acc[0][n0], ah0, b0l);
                mma16816(acc[0][n1], ah0, b1h);
                mma16816(acc[0][n1], ah0, b1l);
                mma16816(acc[1][n0], ah1, b0h);
                mma16816(acc[1][n0], ah1, b0l);
                mma16816(acc[1][n1], ah1, b1h);
                mma16816(acc[1][n1], ah1, b1l);
            }
        }
    }

    // ---- epilogue ----
    if (mode == 3) {
        #pragma unroll
        for (int mi = 0; mi < 2; mi++) {
            #pragma unroll
            for (int ni = 0; ni < 8; ni++) {
                int m0 = rowBase + warpM * 32 + mi * 16 + gid;
                int n0 = colBase + warpN * 64 + ni * 8 + tig * 2;
                #pragma unroll
                for (int e = 0; e < 4; e++) {
                    int m = m0 + ((e >> 1) ? 8 : 0);
                    int n = n0 + (e & 1);
                    outp[(size_t)m * Cc + n] = acc[mi][ni][e] + bias[n];
                }
            }
        }
    } else if (mode == 0) {
        // Q: hi only, scaled 1/8
        #pragma unroll
        for (int mi = 0; mi < 2; mi++) {
            #pragma unroll
            for (int ni = 0; ni < 8; ni++) {
                int m0 = rowBase + warpM * 32 + mi * 16 + gid;
                int n0 = colBase + warpN * 64 + ni * 8 + tig * 2;
                #pragma unroll
                for (int half = 0; half < 2; half++) {
                    int m = m0 + half * 8;
                    float v0 = (acc[mi][ni][half*2+0] + bias[n0])   * 0.125f;
                    float v1 = (acc[mi][ni][half*2+1] + bias[n0+1]) * 0.125f;
                    int b = m >> 11, t = m & 2047;
                    int h = n0 >> 6, d = n0 & 63;
                    size_t off = (((size_t)(b * Hh + h)) * Tt + t) * Dd + d;
                    *(uint32_t*)(g_qh + off) = pk(v0, v1);
                }
            }
        }
    } else {
        __half* dh = (mode == 1) ? g_kh : g_vh;
        __half* dl = (mode == 1) ? g_kl : g_vl;

        #pragma unroll
        for (int mi = 0; mi < 2; mi++) {
            #pragma unroll
            for (int ni = 0; ni < 8; ni++) {
                int m0 = rowBase + warpM * 32 + mi * 16 + gid;
                int n0 = colBase + warpN * 64 + ni * 8 + tig * 2;
                #pragma unroll
                for (int half = 0; half < 2; half++) {
                    int m = m0 + half * 8;
                    float v0 = acc[mi][ni][half*2+0] + bias[n0];
                    float v1 = acc[mi][ni][half*2+1] + bias[n0+1];
                    __half h0 = __float2half_rn(v0);
                    __half h1 = __float2half_rn(v1);
                    int b = m >> 11, t = m & 2047;
                    int h = n0 >> 6, d = n0 & 63;
                    size_t off = (((size_t)(b * Hh + h)) * Tt + t) * Dd + d;
                    __half2 hp; hp.x = h0; hp.y = h1;
                    *(uint32_t*)(dh + off) = *(uint32_t*)&hp;
                    *(uint32_t*)(dl + off) = pk(v0 - __half2float(h0),
                                                v1 - __half2float(h1));
                }
            }
        }
    }
}

// ---------------------------------------------------------------------------
// Flash attention, 2-term fp16, causal, cp.async, single-bar pipeline.
// S = qh.(kh + kl).  PV = ph.(vh + vl).
// Grid (16, 64), 256 threads (8 warps x 16 q-rows). K/V tiles of 64 keys.
// ---------------------------------------------------------------------------
#define ABUFSZ 36864
#define ATT_ARR (64*72*2)     // 9216 B per array

__global__ __launch_bounds__(256, 1) void attn_mma()
{
    extern __shared__ char sm[];
    const uint32_t sbase = sptr(sm);

    const int bh = blockIdx.y;
    const int qblk = (int)gridDim.x - 1 - (int)blockIdx.x;
    const int tid = threadIdx.x;
    const int warp = tid >> 5;
    const int lane = tid & 31;
    const int g = lane >> 2;
    const int tig = lane & 3;

    const size_t base = (size_t)bh * Tt * Dd;

    // ---- stage Q tile (hi only, 128 rows x 64 cols) into buf0 ----
    {
        __half* sQh = (__half*)sm;
        #pragma unroll
        for (int it = 0; it < 4; it++) {          // FIX: 1024 uint4 = full 128-row tile
            int idx = tid + it * 256;             // 0..1023
            int r = idx >> 3, c8 = (idx & 7) * 8; // r: 0..127
            size_t goff = base + (size_t)(qblk*128 + r) * Dd + c8;
            *(uint4*)(sQh + r*72 + c8) = *(const uint4*)(g_qh + goff);
        }
    }
    __syncthreads();

    uint32_t qfh[4][4];
    {
        __half* sQh = (__half*)sm;
        int row = warp*16 + (lane & 15);
        #pragma unroll
        for (int kt = 0; kt < 4; kt++) {
            int col = kt*16 + (lane >> 4) * 8;
            ldm4(qfh[kt], sptr(sQh + row*72 + col));
        }
    }
    __syncthreads();

    float o[8][4];
    #pragma unroll
    for (int i = 0; i < 8; i++)
        #pragma unroll
        for (int j = 0; j < 4; j++) o[i][j] = 0.0f;

    float mA = -INFINITY, mB = -INFINITY, lA = 0.0f, lB = 0.0f;
    const int wr0 = qblk*128 + warp*16;
    const int ntiles = 2*qblk + 2;

    auto load_kv = [&](int kb, int buf) {
        const uint32_t bb = sbase + buf * ABUFSZ;
        #pragma unroll
        for (int it = 0; it < 2; it++) {
            int idx = tid + it * 256;
            int r = idx >> 3, c8 = (idx & 7) * 8;
            size_t goff = base + (size_t)(kb + r) * Dd + c8;
            uint32_t so = (r*72 + c8) * 2;
            cpa16(bb + 0*ATT_ARR + so, g_kh + goff);
            cpa16(bb + 1*ATT_ARR + so, g_kl + goff);
            cpa16(bb + 2*ATT_ARR + so, g_vh + goff);
            cpa16(bb + 3*ATT_ARR + so, g_vl + goff);
        }
    };

    load_kv(0, 0);
    CP_COMMIT();

    for (int ti = 0; ti < ntiles; ti++) {
        const int kb = ti * 64;
        CP_WAIT0();
        __syncthreads();
        if (ti + 1 < ntiles) { load_kv(kb + 64, (ti + 1) & 1); CP_COMMIT(); }

        const char* bb = sm + (ti & 1) * ABUFSZ;
        const __half* sKh = (const __half*)(bb + 0*ATT_ARR);
        const __half* sKl = (const __half*)(bb + 1*ATT_ARR);
        const __half* sVh = (const __half*)(bb + 2*ATT_ARR);
        const __half* sVl = (const __half*)(bb + 3*ATT_ARR);

        // ---- S = qh (kh + kl)^T (2-term) ----
        float s[8][4];
        #pragma unroll
        for (int i = 0; i < 8; i++)
            #pragma unroll
            for (int j = 0; j < 4; j++) s[i][j] = 0.0f;

        #pragma unroll
        for (int kt = 0; kt < 4; kt++) {
            uint32_t kh4[4][4], kl4[4][4];
            #pragma unroll
            for (int i = 0; i < 4; i++) {
                int row = i*16 + (lane & 15);
                int col = kt*16 + (lane >> 4) * 8;
                ldm4(kh4[i], sptr(sKh + row*72 + col));
                ldm4(kl4[i], sptr(sKl + row*72 + col));
            }
            #pragma unroll
            for (int i = 0; i < 4; i++) {
                uint32_t b0h[2] = {kh4[i][0], kh4[i][2]};
                uint32_t b1h[2] = {kh4[i][1], kh4[i][3]};
                uint32_t b0l[2] = {kl4[i][0], kl4[i][2]};
                uint32_t b1l[2] = {kl4[i][1], kl4[i][3]};
                mma16816(s[2*i],   qfh[kt], b0h);
                mma16816(s[2*i],   qfh[kt], b0l);
                mma16816(s[2*i+1], qfh[kt], b1h);
                mma16816(s[2*i+1], qfh[kt], b1l);
            }
        }

        // ---- causal mask ----
        if (kb + 64 > wr0) {
            int rA = wr0 + g, rB = rA + 8;
            #pragma unroll
            for (int nt = 0; nt < 8; nt++) {
                int c0 = kb + nt*8 + tig*2;
                if (c0     > rA) s[nt][0] = -INFINITY;
                if (c0 + 1 > rA) s[nt][1] = -INFINITY;
                if (c0     > rB) s[nt][2] = -INFINITY;
                if (c0 + 1 > rB) s[nt][3] = -INFINITY;
            }
        }

        // ---- online softmax ----
        float ma = -INFINITY, mb = -INFINITY;
        #pragma unroll
        for (int nt = 0; nt < 8; nt++) {
            ma = fmaxf(ma, fmaxf(s[nt][0], s[nt][1]));
            mb = fmaxf(mb, fmaxf(s[nt][2], s[nt][3]));
        }
        ma = fmaxf(ma, __shfl_xor_sync(0xffffffff, ma, 1));
        ma = fmaxf(ma, __shfl_xor_sync(0xffffffff, ma, 2));
        mb = fmaxf(mb, __shfl_xor_sync(0xffffffff, mb, 1));
        mb = fmaxf(mb, __shfl_xor_sync(0xffffffff, mb, 2));

        float nmA = fmaxf(mA, ma), nmB = fmaxf(mB, mb);
        float cA = __expf(mA - nmA), cB = __expf(mB - nmB);
        mA = nmA; mB = nmB;
        lA *= cA; lB *= cB;
        #pragma unroll
        for (int nt = 0; nt < 8; nt++) {
            o[nt][0] *= cA; o[nt][1] *= cA;
            o[nt][2] *= cB; o[nt][3] *= cB;
        }

        // ---- p = exp(s - m), fp16 ----
        uint32_t pah[4][4];
        float suA = 0.0f, suB = 0.0f;
        #pragma unroll
        for (int nt = 0; nt < 8; nt++) {
            float p0 = __expf(s[nt][0] - nmA);
            float p1 = __expf(s[nt][1] - nmA);
            float p2 = __expf(s[nt][2] - nmB);
            float p3 = __expf(s[nt][3] - nmB);
            suA += p0 + p1; suB += p2 + p3;
            int kt = nt >> 1, hi2 = (nt & 1) * 2;
            pah[kt][hi2 + 0] = pk(p0, p1);
            pah[kt][hi2 + 1] = pk(p2, p3);
        }
        suA += __shfl_xor_sync(0xffffffff, suA, 1);
        suA += __shfl_xor_sync(0xffffffff, suA, 2);
        suB += __shfl_xor_sync(0xffffffff, suB, 1);
        suB += __shfl_xor_sync(0xffffffff, suB, 2);
        lA += suA; lB += suB;

        // ---- O += P (vh + vl) (2-term) ----
        #pragma unroll
        for (int kt = 0; kt < 4; kt++) {
            uint32_t vh4[4][4], vl4[4][4];
            #pragma unroll
            for (int j = 0; j < 4; j++) {
                int row = kt*16 + (lane & 15);
                int col = j*16 + (lane >> 4) * 8;
                ldm4t(vh4[j], sptr(sVh + row*72 + col));
                ldm4t(vl4[j], sptr(sVl + row*72 + col));
            }
            #pragma unroll
            for (int j = 0; j < 4; j++) {
                uint32_t b0h[2] = {vh4[j][0], vh4[j][1]};
                uint32_t b1h[2] = {vh4[j][2], vh4[j][3]};
                uint32_t b0l[2] = {vl4[j][0], vl4[j][1]};
                uint32_t b1l[2] = {vl4[j][2], vl4[j][3]};
                mma16816(o[2*j],   pah[kt], b0h);
                mma16816(o[2*j],   pah[kt], b0l);
                mma16816(o[2*j+1], pah[kt], b1h);
                mma16816(o[2*j+1], pah[kt], b1l);
            }
        }
    }

    // ---- epilogue: normalize, write y as fp16 (hi only) in [B,T,C] ----
    const float iA = 1.0f / lA, iB = 1.0f / lB;
    const int b = bh >> 4, h = bh & 15;
    const int rA = qblk*128 + warp*16 + g;
    const size_t offA = ((size_t)(b * Tt + rA)) * Cc + h * 64;
    const size_t offB = offA + (size_t)8 * Cc;

    #pragma unroll
    for (int nt = 0; nt < 8; nt++) {
        int c = nt*8 + tig*2;
        *(uint32_t*)(g_yh + offA + c) = pk(o[nt][0] * iA, o[nt][1] * iA);
        *(uint32_t*)(g_yh + offB + c) = pk(o[nt][2] * iB, o[nt][3] * iB);
    }
}

// ---------------------------------------------------------------------------
extern "C" void kernel_launch(void* const* d_in, const int* in_sizes, int n_in,
                              void* d_out, int out_size)
{
    const float* x  = (const float*)d_in[0];
    const float* Wq = (const float*)d_in[1];
    const float* bq = (const float*)d_in[2];
    const float* Wk = (const float*)d_in[3];
    const float* bk = (const float*)d_in[4];
    const float* Wv = (const float*)d_in[5];
    const float* bv = (const float*)d_in[6];
    const float* Wp = (const float*)d_in[7];
    const float* bp = (const float*)d_in[8];
    float* out = (float*)d_out;

    __half *xh, *yh, *wh, *wl;
    cudaGetSymbolAddress((void**)&xh, g_xh);
    cudaGetSymbolAddress((void**)&yh, g_yh);
    cudaGetSymbolAddress((void**)&wh, g_wh);
    cudaGetSymbolAddress((void**)&wl, g_wl);

    cudaFuncSetAttribute(gemm_db, cudaFuncAttributeMaxDynamicSharedMemorySize, G_SMEM);
    cudaFuncSetAttribute(attn_mma, cudaFuncAttributeMaxDynamicSharedMemorySize, 2*ABUFSZ);

    // all splits in one launch
    split_all<<<8192 + 4096, 256>>>(x, Wq, Wk, Wv, Wp);

    // fused QKV: one launch, z = 3 (all 2-term)
    const int nw = Cc * Cc;
    dim3 gQKV(Cc / 128, Mrows / 128, 3);     // 8 x 64 x 3
    gemm_db<<<gQKV, 256, G_SMEM>>>(xh, wh, wl, bq, bk, bv, nullptr, 1);

    dim3 gA(Tt / 128, Bm * Hh);
    attn_mma<<<gA, 256, 2*ABUFSZ>>>();

    // out projection (2-term)
    dim3 gO(Cc / 128, Mrows / 128, 1);       // 8 x 64
    gemm_db<<<gO, 256, G_SMEM>>>(yh, wh + 3*nw, wl + 3*nw, bp, bp, bp, out, 0);
}

// round 14
// speedup vs baseline: 1.8298x; 1.0112x over previous
#include <cuda_runtime.h>
#include <cuda_fp16.h>
#include <math.h>
#include <stdint.h>

#define Bm 4
#define Tt 2048
#define Cc 1024
#define Hh 16
#define Dd 64
#define Mrows (Bm*Tt)   // 8192

// ------------------------- device-global scratch (fp16) ---------------------
__device__ __half g_qh[Bm*Hh*Tt*Dd];  // [B,H,T,D] hi (pre-scaled 1/8), no lo
__device__ __half g_kh[Bm*Hh*Tt*Dd];
__device__ __half g_kl[Bm*Hh*Tt*Dd];
__device__ __half g_vh[Bm*Hh*Tt*Dd];
__device__ __half g_vl[Bm*Hh*Tt*Dd];

__device__ __half g_xh[Mrows*Cc];
__device__ __half g_yh[Mrows*Cc];      // attention output (hi only)
__device__ __half g_wh[4*Cc*Cc];
__device__ __half g_wl[4*Cc*Cc];

// ---------------------------------------------------------------------------
// fused split kernel: x -> fp16 hi only; weights -> fp16 hi + lo
// ---------------------------------------------------------------------------
__global__ void split_all(const float* __restrict__ x,
                          const float* __restrict__ Wq, const float* __restrict__ Wk,
                          const float* __restrict__ Wv, const float* __restrict__ Wp)
{
    const int bi = blockIdx.x;
    const int tid = threadIdx.x;

    if (bi < 8192) {
        int i = (bi * 256 + tid) * 4;
        float4 v = *(const float4*)(x + i);
        __half2 a; a.x = __float2half_rn(v.x); a.y = __float2half_rn(v.y);
        __half2 b; b.x = __float2half_rn(v.z); b.y = __float2half_rn(v.w);
        *(uint32_t*)(g_xh + i)     = *(uint32_t*)&a;
        *(uint32_t*)(g_xh + i + 2) = *(uint32_t*)&b;
        return;
    }

    int r = bi - 8192;
    int which = r >> 10;
    const float* src = (which == 0) ? Wq : (which == 1) ? Wk : (which == 2) ? Wv : Wp;
    __half* hi = g_wh + (size_t)which * Cc * Cc;
    __half* lo = g_wl + (size_t)which * Cc * Cc;
    int i = (((r & 1023) * 256) + tid) * 4;

    float4 v = *(const float4*)(src + i);
    __half h0 = __float2half_rn(v.x);
    __half h1 = __float2half_rn(v.y);
    __half h2 = __float2half_rn(v.z);
    __half h3 = __float2half_rn(v.w);
    hi[i+0] = h0; hi[i+1] = h1; hi[i+2] = h2; hi[i+3] = h3;
    lo[i+0] = __float2half_rn(v.x - __half2float(h0));
    lo[i+1] = __float2half_rn(v.y - __half2float(h1));
    lo[i+2] = __float2half_rn(v.z - __half2float(h2));
    lo[i+3] = __float2half_rn(v.w - __half2float(h3));
}

// ---------------------------------------------------------------------------
// helpers
// ---------------------------------------------------------------------------
__device__ __forceinline__ uint32_t sptr(const void* p)
{ uint32_t a; asm("{ .reg .u64 t; cvta.to.shared.u64 t, %1; cvt.u32.u64 %0, t; }" : "=r"(a) : "l"(p)); return a; }

__device__ __forceinline__ uint32_t pk(float a, float b)
{
    __half2 t = __floats2half2_rn(a, b);   // a -> low half
    return *(uint32_t*)&t;
}

__device__ __forceinline__ void mma16816(float* c, const uint32_t* a, const uint32_t* b)
{
    asm volatile(
        "mma.sync.aligned.m16n8k16.row.col.f32.f16.f16.f32 "
        "{%0,%1,%2,%3}, {%4,%5,%6,%7}, {%8,%9}, {%0,%1,%2,%3};\n"
        : "+f"(c[0]), "+f"(c[1]), "+f"(c[2]), "+f"(c[3])
        : "r"(a[0]), "r"(a[1]), "r"(a[2]), "r"(a[3]), "r"(b[0]), "r"(b[1]));
}
__device__ __forceinline__ void ldm4(uint32_t* r, uint32_t a)
{
    asm volatile("ldmatrix.sync.aligned.m8n8.x4.shared.b16 {%0,%1,%2,%3}, [%4];"
        : "=r"(r[0]), "=r"(r[1]), "=r"(r[2]), "=r"(r[3]) : "r"(a));
}
__device__ __forceinline__ void ldm4t(uint32_t* r, uint32_t a)
{
    asm volatile("ldmatrix.sync.aligned.m8n8.x4.trans.shared.b16 {%0,%1,%2,%3}, [%4];"
        : "=r"(r[0]), "=r"(r[1]), "=r"(r[2]), "=r"(r[3]) : "r"(a));
}

__device__ __forceinline__ void cpa16(uint32_t dst, const void* src)
{ asm volatile("cp.async.cg.shared.global [%0], [%1], 16;" :: "r"(dst), "l"(src)); }
#define CP_COMMIT() asm volatile("cp.async.commit_group;" ::: "memory")
#define CP_WAIT1()  asm volatile("cp.async.wait_group 1;" ::: "memory")
#define CP_WAIT0()  asm volatile("cp.async.wait_group 0;" ::: "memory")

// ---------------------------------------------------------------------------
// 2-term split-fp16 GEMM: C = Ah @ (Wh + Wl)^T + bias.
// K-stage 32, 3-stage cp.async ring (wait_group 1), ldmatrix frags, 2 CTAs/SM.
// CTA tile 128(M) x 128(N), 8 warps (4M x 2N), warp 32x64.
// Stage: 3 arrays (Ah, Bh, Bl) x 128 rows x 80B pitch = 30720 B; 3 stages.
// fused=1: blockIdx.z selects Wq/Wk/Wv -> epilogue to QKV [B,H,T,D]
//   (mode 0: Q hi only, scaled 1/8; modes 1,2: hi+lo).
// fused=0: fp32 linear to outp.
// ---------------------------------------------------------------------------
#define PE   40              // pitch in fp16 elements (80 B)
#define STG  30720           // stage bytes (3 arrays x 128 rows x 80 B)
#define G_SMEM (3*STG)       // 92160 B -> 2 CTAs/SM (184 KB of 228)

__global__ __launch_bounds__(256, 2) void gemm_db(
    const __half* __restrict__ Ah,
    const __half* __restrict__ Wh, const __half* __restrict__ Wl,
    const float* __restrict__ b0, const float* __restrict__ b1,
    const float* __restrict__ b2,
    float* __restrict__ outp, int fused)
{
    extern __shared__ char smem[];
    const uint32_t sb = sptr(smem);

    const int which = blockIdx.z;
    const __half* __restrict__ Bh = Wh + (size_t)which * Cc * Cc;
    const __half* __restrict__ Bl = Wl + (size_t)which * Cc * Cc;
    const float* __restrict__ bias = (which == 0) ? b0 : (which == 1) ? b1 : b2;
    const int mode = fused ? which : 3;

    const int tid  = threadIdx.x;
    const int warp = tid >> 5;
    const int lane = tid & 31;
    const int warpM = warp & 3;
    const int warpN = warp >> 2;
    const int gid = lane >> 2;
    const int tig = lane & 3;

    const int rowBase = blockIdx.y * 128;
    const int colBase = blockIdx.x * 128;

    float acc[2][8][4];
    #pragma unroll
    for (int i = 0; i < 2; i++)
        #pragma unroll
        for (int j = 0; j < 8; j++)
            #pragma unroll
            for (int k = 0; k < 4; k++) acc[i][j][k] = 0.0f;

    // stage loader: 384 rows x 64B = 1536 cp.async of 16B, 6 per thread
    auto issue = [&](int s, int buf) {
        const int k0 = s * 32;
        const uint32_t bb = sb + buf * STG;
        #pragma unroll
        for (int t = 0; t < 6; t++) {
            int idx = tid + t * 256;          // 0..1535
            int row = idx >> 2;               // 0..383
            int part = idx & 3;
            int arr = row >> 7;               // 0:Ah 1:Bh 2:Bl
            int r = row & 127;
            const __half* src = (arr == 0) ? Ah : (arr == 1) ? Bh : Bl;
            int grow = (arr == 0) ? (rowBase + r) : (colBase + r);
            cpa16(bb + arr * 10240 + r * 80 + part * 16,
                  src + (size_t)grow * Cc + k0 + part * 8);
        }
    };

    issue(0, 0);
    CP_COMMIT();
    issue(1, 1);
    CP_COMMIT();

    int bufs = 0;            // buf index of stage s (cycles 0,1,2)
    for (int s = 0; s < 32; s++) {
        if (s + 1 < 32) { CP_WAIT1(); } else { CP_WAIT0(); }
        __syncthreads();
        if (s + 2 < 32) {
            int b2i = bufs + 2; if (b2i >= 3) b2i -= 3;
            issue(s + 2, b2i);
            CP_COMMIT();
        }

        const char* bb = smem + bufs * STG;
        const __half* sAh = (const __half*)(bb + 0);
        const __half* sBh = (const __half*)(bb + 10240);
        const __half* sBl = (const __half*)(bb + 20480);

        #pragma unroll
        for (int kg = 0; kg < 2; kg++) {
            const int colE = kg * 16 + (lane >> 4) * 8;
            const int arow = warpM * 32 + (lane & 15);

            uint32_t ah0[4], ah1[4];
            ldm4(ah0, sptr(sAh + arow * PE + colE));
            ldm4(ah1, sptr(sAh + (arow + 16) * PE + colE));

            #pragma unroll
            for (int grp = 0; grp < 4; grp++) {
                const int brow = warpN * 64 + grp * 16 + (lane & 15);
                uint32_t th[4], tl[4];
                ldm4(th, sptr(sBh + brow * PE + colE));
                ldm4(tl, sptr(sBl + brow * PE + colE));
                uint32_t b0h[2] = {th[0], th[2]};
                uint32_t b1h[2] = {th[1], th[3]};
                uint32_t b0l[2] = {tl[0], tl[2]};
                uint32_t b1l[2] = {tl[1], tl[3]};
                const int n0 = 2 * grp, n1 = 2 * grp + 1;

                mma16816(acc[0][n0], ah0, b0h);
                mma16816(acc[0][n0], ah0, b0l);
                mma16816(acc[0][n1], ah0, b1h);
                mma16816(acc[0][n1], ah0, b1l);
                mma16816(acc[1][n0], ah1, b0h);
                mma16816(acc[1][n0], ah1, b0l);
                mma16816(acc[1][n1], ah1, b1h);
                mma16816(acc[1][n1], ah1, b1l);
            }
        }
        if (++bufs == 3) bufs = 0;
    }

    // ---- epilogue ----
    if (mode == 3) {
        #pragma unroll
        for (int mi = 0; mi < 2; mi++) {
            #pragma unroll
            for (int ni = 0; ni < 8; ni++) {
                int m0 = rowBase + warpM * 32 + mi * 16 + gid;
                int n0 = colBase + warpN * 64 + ni * 8 + tig * 2;
                #pragma unroll
                for (int e = 0; e < 4; e++) {
                    int m = m0 + ((e >> 1) ? 8 : 0);
                    int n = n0 + (e & 1);
                    outp[(size_t)m * Cc + n] = acc[mi][ni][e] + bias[n];
                }
            }
        }
    } else if (mode == 0) {
        // Q: hi only, scaled 1/8
        #pragma unroll
        for (int mi = 0; mi < 2; mi++) {
            #pragma unroll
            for (int ni = 0; ni < 8; ni++) {
                int m0 = rowBase + warpM * 32 + mi * 16 + gid;
                int n0 = colBase + warpN * 64 + ni * 8 + tig * 2;
                #pragma unroll
                for (int half = 0; half < 2; half++) {
                    int m = m0 + half * 8;
                    float v0 = (acc[mi][ni][half*2+0] + bias[n0])   * 0.125f;
                    float v1 = (acc[mi][ni][half*2+1] + bias[n0+1]) * 0.125f;
                    int b = m >> 11, t = m & 2047;
                    int h = n0 >> 6, d = n0 & 63;
                    size_t off = (((size_t)(b * Hh + h)) * Tt + t) * Dd + d;
                    *(uint32_t*)(g_qh + off) = pk(v0, v1);
                }
            }
        }
    } else {
        __half* dh = (mode == 1) ? g_kh : g_vh;
        __half* dl = (mode == 1) ? g_kl : g_vl;

        #pragma unroll
        for (int mi = 0; mi < 2; mi++) {
            #pragma unroll
            for (int ni = 0; ni < 8; ni++) {
                int m0 = rowBase + warpM * 32 + mi * 16 + gid;
                int n0 = colBase + warpN * 64 + ni * 8 + tig * 2;
                #pragma unroll
                for (int half = 0; half < 2; half++) {
                    int m = m0 + half * 8;
                    float v0 = acc[mi][ni][half*2+0] + bias[n0];
                    float v1 = acc[mi][ni][half*2+1] + bias[n0+1];
                    __half h0 = __float2half_rn(v0);
                    __half h1 = __float2half_rn(v1);
                    int b = m >> 11, t = m & 2047;
                    int h = n0 >> 6, d = n0 & 63;
                    size_t off = (((size_t)(b * Hh + h)) * Tt + t) * Dd + d;
                    __half2 hp; hp.x = h0; hp.y = h1;
                    *(uint32_t*)(dh + off) = *(uint32_t*)&hp;
                    *(uint32_t*)(dl + off) = pk(v0 - __half2float(h0),
                                                v1 - __half2float(h1));
                }
            }
        }
    }
}

// ---------------------------------------------------------------------------
// Flash attention, 2-term fp16, causal, cp.async double-buffer, 2 CTAs/SM.
// S = qh.(kh + kl).  PV = ph.(vh + vl).
// Grid (16, 64), 256 threads (8 warps x 16 q-rows). K/V tiles of 64 keys.
// smem/CTA = 72 KB -> 2 CTAs = 144 KB of 228.
// ---------------------------------------------------------------------------
#define ABUFSZ 36864
#define ATT_ARR (64*72*2)     // 9216 B per array

__global__ __launch_bounds__(256, 2) void attn_mma()
{
    extern __shared__ char sm[];
    const uint32_t sbase = sptr(sm);

    const int bh = blockIdx.y;
    const int qblk = (int)gridDim.x - 1 - (int)blockIdx.x;
    const int tid = threadIdx.x;
    const int warp = tid >> 5;
    const int lane = tid & 31;
    const int g = lane >> 2;
    const int tig = lane & 3;

    const size_t base = (size_t)bh * Tt * Dd;

    // ---- stage Q tile (hi only, 128 rows x 64 cols) into buf0 ----
    {
        __half* sQh = (__half*)sm;
        #pragma unroll
        for (int it = 0; it < 4; it++) {
            int idx = tid + it * 256;             // 0..1023
            int r = idx >> 3, c8 = (idx & 7) * 8; // r: 0..127
            size_t goff = base + (size_t)(qblk*128 + r) * Dd + c8;
            *(uint4*)(sQh + r*72 + c8) = *(const uint4*)(g_qh + goff);
        }
    }
    __syncthreads();

    uint32_t qfh[4][4];
    {
        __half* sQh = (__half*)sm;
        int row = warp*16 + (lane & 15);
        #pragma unroll
        for (int kt = 0; kt < 4; kt++) {
            int col = kt*16 + (lane >> 4) * 8;
            ldm4(qfh[kt], sptr(sQh + row*72 + col));
        }
    }
    __syncthreads();

    float o[8][4];
    #pragma unroll
    for (int i = 0; i < 8; i++)
        #pragma unroll
        for (int j = 0; j < 4; j++) o[i][j] = 0.0f;

    float mA = -INFINITY, mB = -INFINITY, lA = 0.0f, lB = 0.0f;
    const int wr0 = qblk*128 + warp*16;
    const int ntiles = 2*qblk + 2;

    auto load_kv = [&](int kb, int buf) {
        const uint32_t bb = sbase + buf * ABUFSZ;
        #pragma unroll
        for (int it = 0; it < 2; it++) {
            int idx = tid + it * 256;
            int r = idx >> 3, c8 = (idx & 7) * 8;
            size_t goff = base + (size_t)(kb + r) * Dd + c8;
            uint32_t so = (r*72 + c8) * 2;
            cpa16(bb + 0*ATT_ARR + so, g_kh + goff);
            cpa16(bb + 1*ATT_ARR + so, g_kl + goff);
            cpa16(bb + 2*ATT_ARR + so, g_vh + goff);
            cpa16(bb + 3*ATT_ARR + so, g_vl + goff);
        }
    };

    load_kv(0, 0);
    CP_COMMIT();

    for (int ti = 0; ti < ntiles; ti++) {
        const int kb = ti * 64;
        CP_WAIT0();
        __syncthreads();
        if (ti + 1 < ntiles) { load_kv(kb + 64, (ti + 1) & 1); CP_COMMIT(); }

        const char* bb = sm + (ti & 1) * ABUFSZ;
        const __half* sKh = (const __half*)(bb + 0*ATT_ARR);
        const __half* sKl = (const __half*)(bb + 1*ATT_ARR);
        const __half* sVh = (const __half*)(bb + 2*ATT_ARR);
        const __half* sVl = (const __half*)(bb + 3*ATT_ARR);

        // ---- S = qh (kh + kl)^T (2-term) ----
        float s[8][4];
        #pragma unroll
        for (int i = 0; i < 8; i++)
            #pragma unroll
            for (int j = 0; j < 4; j++) s[i][j] = 0.0f;

        #pragma unroll
        for (int kt = 0; kt < 4; kt++) {
            uint32_t kh4[4][4], kl4[4][4];
            #pragma unroll
            for (int i = 0; i < 4; i++) {
                int row = i*16 + (lane & 15);
                int col = kt*16 + (lane >> 4) * 8;
                ldm4(kh4[i], sptr(sKh + row*72 + col));
                ldm4(kl4[i], sptr(sKl + row*72 + col));
            }
            #pragma unroll
            for (int i = 0; i < 4; i++) {
                uint32_t b0h[2] = {kh4[i][0], kh4[i][2]};
                uint32_t b1h[2] = {kh4[i][1], kh4[i][3]};
                uint32_t b0l[2] = {kl4[i][0], kl4[i][2]};
                uint32_t b1l[2] = {kl4[i][1], kl4[i][3]};
                mma16816(s[2*i],   qfh[kt], b0h);
                mma16816(s[2*i],   qfh[kt], b0l);
                mma16816(s[2*i+1], qfh[kt], b1h);
                mma16816(s[2*i+1], qfh[kt], b1l);
            }
        }

        // ---- causal mask ----
        if (kb + 64 > wr0) {
            int rA = wr0 + g, rB = rA + 8;
            #pragma unroll
            for (int nt = 0; nt < 8; nt++) {
                int c0 = kb + nt*8 + tig*2;
                if (c0     > rA) s[nt][0] = -INFINITY;
                if (c0 + 1 > rA) s[nt][1] = -INFINITY;
                if (c0     > rB) s[nt][2] = -INFINITY;
                if (c0 + 1 > rB) s[nt][3] = -INFINITY;
            }
        }

        // ---- online softmax ----
        float ma = -INFINITY, mb = -INFINITY;
        #pragma unroll
        for (int nt = 0; nt < 8; nt++) {
            ma = fmaxf(ma, fmaxf(s[nt][0], s[nt][1]));
            mb = fmaxf(mb, fmaxf(s[nt][2], s[nt][3]));
        }
        ma = fmaxf(ma, __shfl_xor_sync(0xffffffff, ma, 1));
        ma = fmaxf(ma, __shfl_xor_sync(0xffffffff, ma, 2));
        mb = fmaxf(mb, __shfl_xor_sync(0xffffffff, mb, 1));
        mb = fmaxf(mb, __shfl_xor_sync(0xffffffff, mb, 2));

        float nmA = fmaxf(mA, ma), nmB = fmaxf(mB, mb);
        float cA = __expf(mA - nmA), cB = __expf(mB - nmB);
        mA = nmA; mB = nmB;
        lA *= cA; lB *= cB;
        #pragma unroll
        for (int nt = 0; nt < 8; nt++) {
            o[nt][0] *= cA; o[nt][1] *= cA;
            o[nt][2] *= cB; o[nt][3] *= cB;
        }

        // ---- p = exp(s - m), fp16 ----
        uint32_t pah[4][4];
        float suA = 0.0f, suB = 0.0f;
        #pragma unroll
        for (int nt = 0; nt < 8; nt++) {
            float p0 = __expf(s[nt][0] - nmA);
            float p1 = __expf(s[nt][1] - nmA);
            float p2 = __expf(s[nt][2] - nmB);
            float p3 = __expf(s[nt][3] - nmB);
            suA += p0 + p1; suB += p2 + p3;
            int kt = nt >> 1, hi2 = (nt & 1) * 2;
            pah[kt][hi2 + 0] = pk(p0, p1);
            pah[kt][hi2 + 1] = pk(p2, p3);
        }
        suA += __shfl_xor_sync(0xffffffff, suA, 1);
        suA += __shfl_xor_sync(0xffffffff, suA, 2);
        suB += __shfl_xor_sync(0xffffffff, suB, 1);
        suB += __shfl_xor_sync(0xffffffff, suB, 2);
        lA += suA; lB += suB;

        // ---- O += P (vh + vl) (2-term) ----
        #pragma unroll
        for (int kt = 0; kt < 4; kt++) {
            uint32_t vh4[4][4], vl4[4][4];
            #pragma unroll
            for (int j = 0; j < 4; j++) {
                int row = kt*16 + (lane & 15);
                int col = j*16 + (lane >> 4) * 8;
                ldm4t(vh4[j], sptr(sVh + row*72 + col));
                ldm4t(vl4[j], sptr(sVl + row*72 + col));
            }
            #pragma unroll
            for (int j = 0; j < 4; j++) {
                uint32_t b0h[2] = {vh4[j][0], vh4[j][1]};
                uint32_t b1h[2] = {vh4[j][2], vh4[j][3]};
                uint32_t b0l[2] = {vl4[j][0], vl4[j][1]};
                uint32_t b1l[2] = {vl4[j][2], vl4[j][3]};
                mma16816(o[2*j],   pah[kt], b0h);
                mma16816(o[2*j],   pah[kt], b0l);
                mma16816(o[2*j+1], pah[kt], b1h);
                mma16816(o[2*j+1], pah[kt], b1l);
            }
        }
    }

    // ---- epilogue: normalize, write y as fp16 (hi only) in [B,T,C] ----
    const float iA = 1.0f / lA, iB = 1.0f / lB;
    const int b = bh >> 4, h = bh & 15;
    const int rA = qblk*128 + warp*16 + g;
    const size_t offA = ((size_t)(b * Tt + rA)) * Cc + h * 64;
    const size_t offB = offA + (size_t)8 * Cc;

    #pragma unroll
    for (int nt = 0; nt < 8; nt++) {
        int c = nt*8 + tig*2;
        *(uint32_t*)(g_yh + offA + c) = pk(o[nt][0] * iA, o[nt][1] * iA);
        *(uint32_t*)(g_yh + offB + c) = pk(o[nt][2] * iB, o[nt][3] * iB);
    }
}

// ---------------------------------------------------------------------------
extern "C" void kernel_launch(void* const* d_in, const int* in_sizes, int n_in,
                              void* d_out, int out_size)
{
    const float* x  = (const float*)d_in[0];
    const float* Wq = (const float*)d_in[1];
    const float* bq = (const float*)d_in[2];
    const float* Wk = (const float*)d_in[3];
    const float* bk = (const float*)d_in[4];
    const float* Wv = (const float*)d_in[5];
    const float* bv = (const float*)d_in[6];
    const float* Wp = (const float*)d_in[7];
    const float* bp = (const float*)d_in[8];
    float* out = (float*)d_out;

    __half *xh, *yh, *wh, *wl;
    cudaGetSymbolAddress((void**)&xh, g_xh);
    cudaGetSymbolAddress((void**)&yh, g_yh);
    cudaGetSymbolAddress((void**)&wh, g_wh);
    cudaGetSymbolAddress((void**)&wl, g_wl);

    cudaFuncSetAttribute(gemm_db, cudaFuncAttributeMaxDynamicSharedMemorySize, G_SMEM);
    cudaFuncSetAttribute(attn_mma, cudaFuncAttributeMaxDynamicSharedMemorySize, 2*ABUFSZ);

    // all splits in one launch
    split_all<<<8192 + 4096, 256>>>(x, Wq, Wk, Wv, Wp);

    // fused QKV: one launch, z = 3 (all 2-term)
    const int nw = Cc * Cc;
    dim3 gQKV(Cc / 128, Mrows / 128, 3);     // 8 x 64 x 3
    gemm_db<<<gQKV, 256, G_SMEM>>>(xh, wh, wl, bq, bk, bv, nullptr, 1);

    dim3 gA(Tt / 128, Bm * Hh);
    attn_mma<<<gA, 256, 2*ABUFSZ>>>();

    // out projection (2-term)
    dim3 gO(Cc / 128, Mrows / 128, 1);       // 8 x 64
    gemm_db<<<gO, 256, G_SMEM>>>(yh, wh + 3*nw, wl + 3*nw, bp, bp, bp, out, 0);
}